// round 10
// baseline (speedup 1.0000x reference)
#include <cuda_runtime.h>
#include <math.h>
#include <stdint.h>

// Problem constants
#define NB 32
#define ND 64
#define NT 4096
#define NK 512
#define NTOK (NB * NT)          // 131072 tokens
#define TM 256                  // tokens per CTA tile
#define NTILE (NTOK / TM)       // 512 CTAs
#define ESTR 68                 // smem row stride (floats): conflict-free fragment LDS

// Output layout (float32, reference tuple flattened in order)
#define Q_OFF     ((size_t)1)
#define PERP_OFF  ((size_t)1 + (size_t)NB * ND * NT)
#define IDX_OFF   (PERP_OFF + 1)

// Margin threshold: raw-bit tf32 truncation gives dist err <~0.08 each, 2 dists
// + sloppy norms < 0.2; THETA = 0.35 cushion. Flagged tokens -> exact cleanup.
#define THETA 0.35f
#define FLAG_CAP 32768

__device__ float g_loss;
__device__ unsigned int g_counts[NK];
__device__ unsigned int g_flagn;
__device__ int g_flags[FLAG_CAP];

// m16n8k8 tf32 mma: D += A(16x8,row) * B(8x8,col). Operands are raw f32 bit
// patterns; HW uses the top 19 bits (truncation ~2^-11 rel, covered by THETA).
__device__ __forceinline__ void mma_tf32(float* d, const uint32_t* a, const uint32_t* b) {
    asm volatile(
        "mma.sync.aligned.m16n8k8.row.col.f32.tf32.tf32.f32 "
        "{%0,%1,%2,%3}, {%4,%5,%6,%7}, {%8,%9}, {%0,%1,%2,%3};"
        : "+f"(d[0]), "+f"(d[1]), "+f"(d[2]), "+f"(d[3])
        : "r"(a[0]), "r"(a[1]), "r"(a[2]), "r"(a[3]), "r"(b[0]), "r"(b[1]));
}

// ================= K0: init =================
__global__ void vq_init() {
    int i = threadIdx.x;
    if (i == 0) { g_loss = 0.f; g_flagn = 0u; }
    if (i < NK) g_counts[i] = 0u;
}

// ================= K1: tf32 mma GEMM + argmin + margin flag =================
__global__ __launch_bounds__(512, 1) void vq_gemm(
    const float* __restrict__ in, const float* __restrict__ emb,
    float* __restrict__ out)
{
    extern __shared__ float smem[];
    float* sA = smem;                       // TM x ESTR  = 17408 f
    float* sB = sA + TM * ESTR;             // NK x ESTR  = 34816 f
    float* sEn = sB + NK * ESTR;            // NK
    float* sXn = sEn + NK;                  // TM

    const int tid = threadIdx.x;
    const int wid = tid >> 5;
    const int lane = tid & 31;
    const int grp = lane >> 2;              // 0..7  (fragment row group)
    const int qid = lane & 3;               // 0..3  (fragment k/col slot)

    const int token0 = blockIdx.x * TM;
    const int b = token0 >> 12;             // tile within one batch (4096%256==0)
    const int t0 = token0 & (NT - 1);

    // ---- Stage B (raw f32 codebook), all threads, float4 ----
    {
        const float4* e4 = (const float4*)emb;
        for (int i = tid; i < NK * ND / 4; i += 512) {
            int code = i >> 4, d4 = i & 15;
            float4 v = e4[i];
            *(float4*)(sB + code * ESTR + 4 * d4) = v;
        }
    }
    // ---- Stage A + sloppy xn : threads 0..255 (one token each) ----
    if (tid < TM) {
        const float* xp = in + (size_t)b * ND * NT + (t0 + tid);
        float xn = 0.f;
        float* ar = sA + tid * ESTR;
        #pragma unroll
        for (int d = 0; d < ND; d++) {
            float x = xp[(size_t)d * NT];                 // coalesced
            xn = __fmaf_rn(x, x, xn);                     // sloppy ok (THETA covers)
            ar[d] = x;
        }
        sXn[tid] = xn;
    } else {
        // ---- sloppy en : threads 256..511, two codes each ----
        for (int k = tid - 256; k < NK; k += 256) {
            const float* e = emb + k * ND;
            float s = 0.f;
            #pragma unroll
            for (int d = 0; d < ND; d++) s = __fmaf_rn(e[d], e[d], s);
            sEn[k] = s;
        }
    }
    __syncthreads();

    // ---- A fragments (raw f32 bits) : warp owns m-block wid*16 ----
    const int m0 = wid * 16;
    uint32_t ah[8][4];
    #pragma unroll
    for (int kk = 0; kk < 8; kk++) {
        const float* r0 = sA + (m0 + grp) * ESTR + kk * 8;
        const float* r8 = sA + (m0 + grp + 8) * ESTR + kk * 8;
        ah[kk][0] = __float_as_uint(r0[qid]);
        ah[kk][1] = __float_as_uint(r8[qid]);
        ah[kk][2] = __float_as_uint(r0[qid + 4]);
        ah[kk][3] = __float_as_uint(r8[qid + 4]);
    }
    const float xnA = sXn[m0 + grp];
    const float xnB = sXn[m0 + grp + 8];

    float bA = 3.4e38f, sA2 = 3.4e38f; int iA = 0;
    float bB = 3.4e38f, sB2 = 3.4e38f; int iB = 0;

    // ---- n-loop: 64 tiles of 8 codes, single mma per kstep ----
    #pragma unroll 1
    for (int n0 = 0; n0 < NK; n0 += 8) {
        float acc[4] = {0.f, 0.f, 0.f, 0.f};
        const float* bp = sB + (n0 + grp) * ESTR;
        #pragma unroll
        for (int kk = 0; kk < 8; kk++) {
            uint32_t bb[2] = { __float_as_uint(bp[kk * 8 + qid]),
                               __float_as_uint(bp[kk * 8 + qid + 4]) };
            mma_tf32(acc, ah[kk], bb);
        }
        const int c0 = n0 + 2 * qid;
        const float en0 = sEn[c0], en1 = sEn[c0 + 1];
        float d0 = (xnA + en0) - 2.f * acc[0];
        float d1 = (xnA + en1) - 2.f * acc[1];
        float d2 = (xnB + en0) - 2.f * acc[2];
        float d3 = (xnB + en1) - 2.f * acc[3];
        if (d0 < bA) { sA2 = bA; bA = d0; iA = c0; } else if (d0 < sA2) sA2 = d0;
        if (d1 < bA) { sA2 = bA; bA = d1; iA = c0 + 1; } else if (d1 < sA2) sA2 = d1;
        if (d2 < bB) { sB2 = bB; bB = d2; iB = c0; } else if (d2 < sB2) sB2 = d2;
        if (d3 < bB) { sB2 = bB; bB = d3; iB = c0 + 1; } else if (d3 < sB2) sB2 = d3;
    }

    // ---- merge across the 4 lanes of each row-group (tie -> lower index) ----
    #pragma unroll
    for (int m = 1; m <= 2; m <<= 1) {
        float ob = __shfl_xor_sync(0xffffffffu, bA, m);
        float os = __shfl_xor_sync(0xffffffffu, sA2, m);
        int   oi = __shfl_xor_sync(0xffffffffu, iA, m);
        if (ob < bA || (ob == bA && oi < iA)) { sA2 = fminf(bA, os); bA = ob; iA = oi; }
        else { sA2 = fminf(sA2, ob); }
        ob = __shfl_xor_sync(0xffffffffu, bB, m);
        os = __shfl_xor_sync(0xffffffffu, sB2, m);
        oi = __shfl_xor_sync(0xffffffffu, iB, m);
        if (ob < bB || (ob == bB && oi < iB)) { sB2 = fminf(bB, os); bB = ob; iB = oi; }
        else { sB2 = fminf(sB2, ob); }
    }

    if (qid == 0) {
        int tokA = token0 + m0 + grp;
        int tokB = tokA + 8;
        out[IDX_OFF + (size_t)tokA] = (float)iA;
        out[IDX_OFF + (size_t)tokB] = (float)iB;
        if (!(sA2 - bA > THETA)) {          // tiny margin (or NaN) -> exact path
            unsigned p = atomicAdd(&g_flagn, 1u);
            if (p < FLAG_CAP) g_flags[p] = tokA;
        }
        if (!(sB2 - bB > THETA)) {
            unsigned p = atomicAdd(&g_flagn, 1u);
            if (p < FLAG_CAP) g_flags[p] = tokB;
        }
    }
}

// ============ K2: exact frozen recompute for flagged tokens (4 slots/CTA) ============
// Runs BEFORE gather: only fixes indices; gather derives q/loss/hist from them.
__global__ __launch_bounds__(512, 1) void vq_cleanup(
    const float* __restrict__ in, const float* __restrict__ emb,
    float* __restrict__ out)
{
    __shared__ float sen[NK];
    __shared__ float sx[4][ND];
    __shared__ float sxn[4];
    __shared__ unsigned long long skey[4];

    const int tid = threadIdx.x;
    const int wid = tid >> 5;
    const int lane = tid & 31;
    const int slot = tid >> 7;     // 0..3
    const int st = tid & 127;

    // FROZEN en (warp-tree, matches reference rounding: no-fma + shfl tree)
    for (int k = wid; k < NK; k += 16) {
        const float* e = emb + k * ND;
        float a = __fmul_rn(e[lane], e[lane]);
        float c = __fmul_rn(e[lane + 32], e[lane + 32]);
        float acc = __fadd_rn(a, c);
        #pragma unroll
        for (int off = 16; off; off >>= 1)
            acc = __fadd_rn(acc, __shfl_down_sync(0xffffffffu, acc, off));
        if (lane == 0) sen[k] = acc;
    }
    __syncthreads();

    unsigned count = g_flagn;
    if (count > FLAG_CAP) count = FLAG_CAP;
    const unsigned gslots = gridDim.x * 4;
    const unsigned iters = (count + gslots - 1) / gslots;

    for (unsigned it = 0; it < iters; it++) {
        const unsigned fi = it * gslots + blockIdx.x * 4 + slot;
        const bool act = fi < count;
        int token = 0;
        if (act) {
            token = g_flags[fi];
            int b = token >> 12, t = token & (NT - 1);
            if (st < ND) sx[slot][st] = in[(size_t)b * ND * NT + (size_t)st * NT + t];
            if (st == 0) skey[slot] = 0xFFFFFFFFFFFFFFFFull;
        }
        __syncthreads();
        if (act && st == 0) {
            float xn = 0.f;   // FROZEN: sequential ascending, no fma contraction
            for (int d = 0; d < ND; d++)
                xn = __fadd_rn(xn, __fmul_rn(sx[slot][d], sx[slot][d]));
            sxn[slot] = xn;
        }
        __syncthreads();
        if (act) {
            // thread handles 4 codes: st, st+128, st+256, st+384 (frozen seq fma dot)
            float a0 = 0.f, a1 = 0.f, a2 = 0.f, a3 = 0.f;
            const float* e0 = emb + (st +   0) * ND;
            const float* e1 = emb + (st + 128) * ND;
            const float* e2 = emb + (st + 256) * ND;
            const float* e3 = emb + (st + 384) * ND;
            for (int d = 0; d < ND; d++) {
                float xv = sx[slot][d];
                a0 = __fmaf_rn(xv, e0[d], a0);
                a1 = __fmaf_rn(xv, e1[d], a1);
                a2 = __fmaf_rn(xv, e2[d], a2);
                a3 = __fmaf_rn(xv, e3[d], a3);
            }
            float xn = sxn[slot];
            #pragma unroll
            for (int j = 0; j < 4; j++) {
                float dot = (j == 0) ? a0 : (j == 1) ? a1 : (j == 2) ? a2 : a3;
                int k = st + 128 * j;
                float dist = __fadd_rn(__fadd_rn(xn, sen[k]), __fmul_rn(-2.f, dot));
                uint32_t u = __float_as_uint(dist);
                u = (u & 0x80000000u) ? ~u : (u | 0x80000000u);   // order-preserving
                unsigned long long key = ((unsigned long long)u << 32) | (unsigned)k;
                atomicMin(&skey[slot], key);   // min dist, tie -> min index (first-min)
            }
        }
        __syncthreads();
        if (act && st == 0)
            out[IDX_OFF + (size_t)token] = (float)(unsigned)(skey[slot] & 0xFFFFFFFFu);
        __syncthreads();
    }
}

// ================= K3: gather + loss + histogram (from final indices) =================
__global__ __launch_bounds__(512, 1) void vq_gather(
    const float* __restrict__ in, const float* __restrict__ emb,
    float* __restrict__ out)
{
    __shared__ unsigned int sCount[NK];
    __shared__ float sLoss;
    const int tid = threadIdx.x;
    if (tid == 0) sLoss = 0.f;
    if (tid < NK) sCount[tid] = 0u;
    __syncthreads();

    const int token = blockIdx.x * 512 + tid;
    const int b = token >> 12, t = token & (NT - 1);
    const int k = (int)out[IDX_OFF + (size_t)token];

    atomicAdd(&sCount[k], 1u);

    const float* xp = in + (size_t)b * ND * NT + t;
    const float4* eb4 = (const float4*)(emb + k * ND);
    float* qp = out + Q_OFF + (size_t)b * ND * NT + t;
    float lsum = 0.f;
    #pragma unroll
    for (int j = 0; j < ND / 4; j++) {
        float4 v = eb4[j];
        float x0 = xp[(size_t)(4 * j + 0) * NT];
        float x1 = xp[(size_t)(4 * j + 1) * NT];
        float x2 = xp[(size_t)(4 * j + 2) * NT];
        float x3 = xp[(size_t)(4 * j + 3) * NT];
        qp[(size_t)(4 * j + 0) * NT] = v.x;
        qp[(size_t)(4 * j + 1) * NT] = v.y;
        qp[(size_t)(4 * j + 2) * NT] = v.z;
        qp[(size_t)(4 * j + 3) * NT] = v.w;
        float t0 = v.x - x0, t1 = v.y - x1, t2 = v.z - x2, t3 = v.w - x3;
        lsum = __fmaf_rn(t0, t0, lsum);
        lsum = __fmaf_rn(t1, t1, lsum);
        lsum = __fmaf_rn(t2, t2, lsum);
        lsum = __fmaf_rn(t3, t3, lsum);
    }
    #pragma unroll
    for (int off = 16; off; off >>= 1)
        lsum += __shfl_down_sync(0xffffffffu, lsum, off);
    if ((tid & 31) == 0) atomicAdd(&sLoss, lsum);
    __syncthreads();
    if (tid == 0) atomicAdd(&g_loss, sLoss);
    if (tid < NK) {
        unsigned c = sCount[tid];
        if (c) atomicAdd(&g_counts[tid], c);
    }
}

// ================= K4: finalize =================
__global__ void vq_final(float* __restrict__ out) {
    __shared__ float red[32];
    int tid = threadIdx.x;
    if (tid < 32) red[tid] = 0.f;
    __syncthreads();
    unsigned c = g_counts[tid];
    float p = (float)c / (float)NTOK;
    float term = p * logf(p + 1e-10f);
    #pragma unroll
    for (int off = 16; off; off >>= 1)
        term += __shfl_down_sync(0xffffffffu, term, off);
    if ((tid & 31) == 0) red[tid >> 5] = term;
    __syncthreads();
    if (tid < 32) {
        float v = red[tid];
        #pragma unroll
        for (int off = 16; off; off >>= 1)
            v += __shfl_down_sync(0xffffffffu, v, off);
        if (tid == 0) {
            out[PERP_OFF] = expf(-v);
            out[0] = 0.25f * g_loss / (float)((size_t)NTOK * ND);
        }
    }
}

extern "C" void kernel_launch(void* const* d_in, const int* in_sizes, int n_in,
                              void* d_out, int out_size) {
    const float* in  = (const float*)d_in[0];   // [32, 64, 4096]
    const float* emb = (const float*)d_in[1];   // [512, 64]
    float* out = (float*)d_out;

    size_t smem = (size_t)(TM * ESTR + NK * ESTR + NK + TM) * sizeof(float);
    cudaFuncSetAttribute(vq_gemm, cudaFuncAttributeMaxDynamicSharedMemorySize, (int)smem);

    vq_init<<<1, 512>>>();
    vq_gemm<<<NTILE, 512, smem>>>(in, emb, out);
    vq_cleanup<<<148, 512>>>(in, emb, out);
    vq_gather<<<NTOK / 512, 512>>>(in, emb, out);
    vq_final<<<1, 512>>>(out);
}

// round 11
// speedup vs baseline: 3.5159x; 3.5159x over previous
#include <cuda_runtime.h>
#include <math.h>
#include <stdint.h>

// Problem constants
#define NB 32
#define ND 64
#define NT 4096
#define NK 512
#define NTOK (NB * NT)          // 131072 tokens
#define TM 256                  // tokens per CTA tile (GEMM)
#define NTILE (NTOK / TM)       // 512 CTAs
#define ESTR 68                 // smem row stride (floats)

// Output layout (float32, reference tuple flattened in order)
#define Q_OFF     ((size_t)1)
#define PERP_OFF  ((size_t)1 + (size_t)NB * ND * NT)
#define IDX_OFF   (PERP_OFF + 1)

// Margin threshold (approx vs frozen distance error cushion). Sound for any
// realistic data; every sub-THETA-margin token is recomputed exactly.
#define THETA 0.5f
#define FLAG_CAP NTOK           // no cap -> no correctness hole

__device__ float g_loss;
__device__ unsigned int g_counts[NK];
__device__ unsigned int g_flagn;
__device__ int g_flags[FLAG_CAP];

// m16n8k8 tf32 mma: D += A(16x8,row) * B(8x8,col). Operands are raw f32 bit
// patterns; HW uses the top 19 bits (truncation ~2^-11 rel, covered by THETA).
__device__ __forceinline__ void mma_tf32(float* d, const uint32_t* a, const uint32_t* b) {
    asm volatile(
        "mma.sync.aligned.m16n8k8.row.col.f32.tf32.tf32.f32 "
        "{%0,%1,%2,%3}, {%4,%5,%6,%7}, {%8,%9}, {%0,%1,%2,%3};"
        : "+f"(d[0]), "+f"(d[1]), "+f"(d[2]), "+f"(d[3])
        : "r"(a[0]), "r"(a[1]), "r"(a[2]), "r"(a[3]), "r"(b[0]), "r"(b[1]));
}

// ================= K0: init =================
__global__ void vq_init() {
    int i = threadIdx.x;
    if (i == 0) { g_loss = 0.f; g_flagn = 0u; }
    if (i < NK) g_counts[i] = 0u;
}

// ================= K1: tf32 mma GEMM + argmin + margin flag =================
__global__ __launch_bounds__(512, 1) void vq_gemm(
    const float* __restrict__ in, const float* __restrict__ emb,
    float* __restrict__ out)
{
    extern __shared__ float smem[];
    float* sA = smem;                       // TM x ESTR
    float* sB = sA + TM * ESTR;             // NK x ESTR
    float* sEn = sB + NK * ESTR;            // NK
    float* sXn = sEn + NK;                  // TM

    const int tid = threadIdx.x;
    const int wid = tid >> 5;
    const int lane = tid & 31;
    const int grp = lane >> 2;              // 0..7
    const int qid = lane & 3;               // 0..3

    const int token0 = blockIdx.x * TM;
    const int b = token0 >> 12;
    const int t0 = token0 & (NT - 1);

    // ---- Stage B (raw f32 codebook) ----
    {
        const float4* e4 = (const float4*)emb;
        for (int i = tid; i < NK * ND / 4; i += 512) {
            int code = i >> 4, d4 = i & 15;
            float4 v = e4[i];
            *(float4*)(sB + code * ESTR + 4 * d4) = v;
        }
    }
    // ---- Stage A + sloppy xn : threads 0..255 ----
    if (tid < TM) {
        const float* xp = in + (size_t)b * ND * NT + (t0 + tid);
        float xn = 0.f;
        float* ar = sA + tid * ESTR;
        #pragma unroll
        for (int d = 0; d < ND; d++) {
            float x = xp[(size_t)d * NT];
            xn = __fmaf_rn(x, x, xn);
            ar[d] = x;
        }
        sXn[tid] = xn;
    } else {
        // ---- sloppy en : threads 256..511 ----
        for (int k = tid - 256; k < NK; k += 256) {
            const float* e = emb + k * ND;
            float s = 0.f;
            #pragma unroll
            for (int d = 0; d < ND; d++) s = __fmaf_rn(e[d], e[d], s);
            sEn[k] = s;
        }
    }
    __syncthreads();

    // ---- A fragments (raw f32 bits) ----
    const int m0 = wid * 16;
    uint32_t ah[8][4];
    #pragma unroll
    for (int kk = 0; kk < 8; kk++) {
        const float* r0 = sA + (m0 + grp) * ESTR + kk * 8;
        const float* r8 = sA + (m0 + grp + 8) * ESTR + kk * 8;
        ah[kk][0] = __float_as_uint(r0[qid]);
        ah[kk][1] = __float_as_uint(r8[qid]);
        ah[kk][2] = __float_as_uint(r0[qid + 4]);
        ah[kk][3] = __float_as_uint(r8[qid + 4]);
    }
    const float xnA = sXn[m0 + grp];
    const float xnB = sXn[m0 + grp + 8];

    float bA = 3.4e38f, sA2 = 3.4e38f; int iA = 0;
    float bB = 3.4e38f, sB2 = 3.4e38f; int iB = 0;

    // ---- n-loop: 64 tiles of 8 codes, single mma per kstep ----
    #pragma unroll 1
    for (int n0 = 0; n0 < NK; n0 += 8) {
        float acc[4] = {0.f, 0.f, 0.f, 0.f};
        const float* bp = sB + (n0 + grp) * ESTR;
        #pragma unroll
        for (int kk = 0; kk < 8; kk++) {
            uint32_t bb[2] = { __float_as_uint(bp[kk * 8 + qid]),
                               __float_as_uint(bp[kk * 8 + qid + 4]) };
            mma_tf32(acc, ah[kk], bb);
        }
        const int c0 = n0 + 2 * qid;
        const float en0 = sEn[c0], en1 = sEn[c0 + 1];
        float d0 = (xnA + en0) - 2.f * acc[0];
        float d1 = (xnA + en1) - 2.f * acc[1];
        float d2 = (xnB + en0) - 2.f * acc[2];
        float d3 = (xnB + en1) - 2.f * acc[3];
        if (d0 < bA) { sA2 = bA; bA = d0; iA = c0; } else if (d0 < sA2) sA2 = d0;
        if (d1 < bA) { sA2 = bA; bA = d1; iA = c0 + 1; } else if (d1 < sA2) sA2 = d1;
        if (d2 < bB) { sB2 = bB; bB = d2; iB = c0; } else if (d2 < sB2) sB2 = d2;
        if (d3 < bB) { sB2 = bB; bB = d3; iB = c0 + 1; } else if (d3 < sB2) sB2 = d3;
    }

    // ---- merge across the 4 lanes of each row-group (tie -> lower index) ----
    #pragma unroll
    for (int m = 1; m <= 2; m <<= 1) {
        float ob = __shfl_xor_sync(0xffffffffu, bA, m);
        float os = __shfl_xor_sync(0xffffffffu, sA2, m);
        int   oi = __shfl_xor_sync(0xffffffffu, iA, m);
        if (ob < bA || (ob == bA && oi < iA)) { sA2 = fminf(bA, os); bA = ob; iA = oi; }
        else { sA2 = fminf(sA2, ob); }
        ob = __shfl_xor_sync(0xffffffffu, bB, m);
        os = __shfl_xor_sync(0xffffffffu, sB2, m);
        oi = __shfl_xor_sync(0xffffffffu, iB, m);
        if (ob < bB || (ob == bB && oi < iB)) { sB2 = fminf(bB, os); bB = ob; iB = oi; }
        else { sB2 = fminf(sB2, ob); }
    }

    if (qid == 0) {
        int tokA = token0 + m0 + grp;
        int tokB = tokA + 8;
        out[IDX_OFF + (size_t)tokA] = (float)iA;
        out[IDX_OFF + (size_t)tokB] = (float)iB;
        if (!(sA2 - bA > THETA)) {          // tiny margin (or NaN) -> exact path
            unsigned p = atomicAdd(&g_flagn, 1u);
            g_flags[p] = tokA;
        }
        if (!(sB2 - bB > THETA)) {
            unsigned p = atomicAdd(&g_flagn, 1u);
            g_flags[p] = tokB;
        }
    }
}

// ======== K2: exact frozen recompute, one flagged token per thread, smem codebook ======
__global__ __launch_bounds__(512, 1) void vq_cleanup(
    const float* __restrict__ in, const float* __restrict__ emb,
    float* __restrict__ out)
{
    extern __shared__ float smem[];
    float* sE = smem;                 // NK x ESTR (raw f32)
    float* sEn = sE + NK * ESTR;      // NK (FROZEN norms)

    const int tid = threadIdx.x;
    const int wid = tid >> 5;
    const int lane = tid & 31;

    // Stage codebook (padded stride)
    {
        const float4* e4 = (const float4*)emb;
        for (int i = tid; i < NK * ND / 4; i += 512) {
            int code = i >> 4, d4 = i & 15;
            float4 v = e4[i];
            *(float4*)(sE + code * ESTR + 4 * d4) = v;
        }
    }
    // FROZEN en: no-fma products, lane sums {l, l+32}, shfl tree 16..1
    for (int k = wid; k < NK; k += 16) {
        const float* e = emb + k * ND;
        float a = __fmul_rn(e[lane], e[lane]);
        float c = __fmul_rn(e[lane + 32], e[lane + 32]);
        float acc = __fadd_rn(a, c);
        #pragma unroll
        for (int off = 16; off; off >>= 1)
            acc = __fadd_rn(acc, __shfl_down_sync(0xffffffffu, acc, off));
        if (lane == 0) sEn[k] = acc;
    }
    __syncthreads();

    const unsigned count = g_flagn;

    for (unsigned fi = blockIdx.x * 512 + tid; fi < count; fi += gridDim.x * 512) {
        const int token = g_flags[fi];
        const int b = token >> 12, t = token & (NT - 1);

        const float* xp = in + (size_t)b * ND * NT + t;
        float x[ND];
        #pragma unroll
        for (int d = 0; d < ND; d++) x[d] = xp[(size_t)d * NT];

        // FROZEN xn: sequential ascending, no fma contraction
        float xn = 0.f;
        #pragma unroll
        for (int d = 0; d < ND; d++) xn = __fadd_rn(xn, __fmul_rn(x[d], x[d]));

        // FROZEN argmin: per-code sequential ascending fma chain, 4 codes ILP,
        // uniform LDS.128 (broadcast), combine fl(fl(xn+en) + fl(-2*dot)), first-min.
        float best = 3.402823466e38f;
        int bidx = 0;
        for (int k0 = 0; k0 < NK; k0 += 4) {
            const float4* e0 = (const float4*)(sE + (k0 + 0) * ESTR);
            const float4* e1 = (const float4*)(sE + (k0 + 1) * ESTR);
            const float4* e2 = (const float4*)(sE + (k0 + 2) * ESTR);
            const float4* e3 = (const float4*)(sE + (k0 + 3) * ESTR);
            float a0 = 0.f, a1 = 0.f, a2 = 0.f, a3 = 0.f;
            #pragma unroll
            for (int j = 0; j < ND / 4; j++) {
                float4 v0 = e0[j], v1 = e1[j], v2 = e2[j], v3 = e3[j];
                a0 = __fmaf_rn(x[4*j+0], v0.x, a0);
                a1 = __fmaf_rn(x[4*j+0], v1.x, a1);
                a2 = __fmaf_rn(x[4*j+0], v2.x, a2);
                a3 = __fmaf_rn(x[4*j+0], v3.x, a3);
                a0 = __fmaf_rn(x[4*j+1], v0.y, a0);
                a1 = __fmaf_rn(x[4*j+1], v1.y, a1);
                a2 = __fmaf_rn(x[4*j+1], v2.y, a2);
                a3 = __fmaf_rn(x[4*j+1], v3.y, a3);
                a0 = __fmaf_rn(x[4*j+2], v0.z, a0);
                a1 = __fmaf_rn(x[4*j+2], v1.z, a1);
                a2 = __fmaf_rn(x[4*j+2], v2.z, a2);
                a3 = __fmaf_rn(x[4*j+2], v3.z, a3);
                a0 = __fmaf_rn(x[4*j+3], v0.w, a0);
                a1 = __fmaf_rn(x[4*j+3], v1.w, a1);
                a2 = __fmaf_rn(x[4*j+3], v2.w, a2);
                a3 = __fmaf_rn(x[4*j+3], v3.w, a3);
            }
            float d0 = __fadd_rn(__fadd_rn(xn, sEn[k0 + 0]), __fmul_rn(-2.f, a0));
            float d1 = __fadd_rn(__fadd_rn(xn, sEn[k0 + 1]), __fmul_rn(-2.f, a1));
            float d2 = __fadd_rn(__fadd_rn(xn, sEn[k0 + 2]), __fmul_rn(-2.f, a2));
            float d3 = __fadd_rn(__fadd_rn(xn, sEn[k0 + 3]), __fmul_rn(-2.f, a3));
            if (d0 < best) { best = d0; bidx = k0 + 0; }
            if (d1 < best) { best = d1; bidx = k0 + 1; }
            if (d2 < best) { best = d2; bidx = k0 + 2; }
            if (d3 < best) { best = d3; bidx = k0 + 3; }
        }
        out[IDX_OFF + (size_t)token] = (float)bidx;
    }
}

// ================= K3: gather + loss + histogram (from final indices) =================
__global__ __launch_bounds__(512, 1) void vq_gather(
    const float* __restrict__ in, const float* __restrict__ emb,
    float* __restrict__ out)
{
    __shared__ unsigned int sCount[NK];
    __shared__ float sLoss;
    const int tid = threadIdx.x;
    if (tid == 0) sLoss = 0.f;
    if (tid < NK) sCount[tid] = 0u;
    __syncthreads();

    const int token = blockIdx.x * 512 + tid;
    const int b = token >> 12, t = token & (NT - 1);
    const int k = (int)out[IDX_OFF + (size_t)token];

    atomicAdd(&sCount[k], 1u);

    const float* xp = in + (size_t)b * ND * NT + t;
    const float4* eb4 = (const float4*)(emb + k * ND);
    float* qp = out + Q_OFF + (size_t)b * ND * NT + t;
    float lsum = 0.f;
    #pragma unroll
    for (int j = 0; j < ND / 4; j++) {
        float4 v = eb4[j];
        float x0 = xp[(size_t)(4 * j + 0) * NT];
        float x1 = xp[(size_t)(4 * j + 1) * NT];
        float x2 = xp[(size_t)(4 * j + 2) * NT];
        float x3 = xp[(size_t)(4 * j + 3) * NT];
        qp[(size_t)(4 * j + 0) * NT] = v.x;
        qp[(size_t)(4 * j + 1) * NT] = v.y;
        qp[(size_t)(4 * j + 2) * NT] = v.z;
        qp[(size_t)(4 * j + 3) * NT] = v.w;
        float t0 = v.x - x0, t1 = v.y - x1, t2 = v.z - x2, t3 = v.w - x3;
        lsum = __fmaf_rn(t0, t0, lsum);
        lsum = __fmaf_rn(t1, t1, lsum);
        lsum = __fmaf_rn(t2, t2, lsum);
        lsum = __fmaf_rn(t3, t3, lsum);
    }
    #pragma unroll
    for (int off = 16; off; off >>= 1)
        lsum += __shfl_down_sync(0xffffffffu, lsum, off);
    if ((tid & 31) == 0) atomicAdd(&sLoss, lsum);
    __syncthreads();
    if (tid == 0) atomicAdd(&g_loss, sLoss);
    if (tid < NK) {
        unsigned c = sCount[tid];
        if (c) atomicAdd(&g_counts[tid], c);
    }
}

// ================= K4: finalize =================
__global__ void vq_final(float* __restrict__ out) {
    __shared__ float red[32];
    int tid = threadIdx.x;
    if (tid < 32) red[tid] = 0.f;
    __syncthreads();
    unsigned c = g_counts[tid];
    float p = (float)c / (float)NTOK;
    float term = p * logf(p + 1e-10f);
    #pragma unroll
    for (int off = 16; off; off >>= 1)
        term += __shfl_down_sync(0xffffffffu, term, off);
    if ((tid & 31) == 0) red[tid >> 5] = term;
    __syncthreads();
    if (tid < 32) {
        float v = red[tid];
        #pragma unroll
        for (int off = 16; off; off >>= 1)
            v += __shfl_down_sync(0xffffffffu, v, off);
        if (tid == 0) {
            out[PERP_OFF] = expf(-v);
            out[0] = 0.25f * g_loss / (float)((size_t)NTOK * ND);
        }
    }
}

extern "C" void kernel_launch(void* const* d_in, const int* in_sizes, int n_in,
                              void* d_out, int out_size) {
    const float* in  = (const float*)d_in[0];   // [32, 64, 4096]
    const float* emb = (const float*)d_in[1];   // [512, 64]
    float* out = (float*)d_out;

    size_t smem_g = (size_t)(TM * ESTR + NK * ESTR + NK + TM) * sizeof(float);
    size_t smem_c = (size_t)(NK * ESTR + NK) * sizeof(float);
    cudaFuncSetAttribute(vq_gemm, cudaFuncAttributeMaxDynamicSharedMemorySize, (int)smem_g);
    cudaFuncSetAttribute(vq_cleanup, cudaFuncAttributeMaxDynamicSharedMemorySize, (int)smem_c);

    vq_init<<<1, 512>>>();
    vq_gemm<<<NTILE, 512, smem_g>>>(in, emb, out);
    vq_cleanup<<<148, 512, smem_c>>>(in, emb, out);
    vq_gather<<<NTOK / 512, 512>>>(in, emb, out);
    vq_final<<<1, 512>>>(out);
}

// round 12
// speedup vs baseline: 3.5330x; 1.0049x over previous
#include <cuda_runtime.h>
#include <math.h>
#include <stdint.h>

// Problem constants
#define NB 32
#define ND 64
#define NT 4096
#define NK 512
#define NTOK (NB * NT)          // 131072 tokens
#define TM 256                  // tokens per CTA tile (GEMM)
#define NTILE (NTOK / TM)       // 512 CTAs
#define ESTR 68                 // smem row stride (floats)

// Output layout (float32, reference tuple flattened in order)
#define Q_OFF     ((size_t)1)
#define PERP_OFF  ((size_t)1 + (size_t)NB * ND * NT)
#define IDX_OFF   (PERP_OFF + 1)

// Margin threshold. Both mma operands are rna-rounded tf32 -> unbiased distance
// error, RMS ~1e-3 (empirical anchor: R3 flips at ~3e-4 margin). 0.05 = ~50x.
#define THETA 0.05f
#define FLAG_CAP NTOK           // uncapped -> no correctness hole

__device__ float g_loss;
__device__ unsigned int g_counts[NK];
__device__ unsigned int g_flagn;
__device__ int g_flags[FLAG_CAP];

__device__ __forceinline__ float tf32r(float v) {
    uint32_t u;
    asm("cvt.rna.tf32.f32 %0, %1;" : "=r"(u) : "f"(v));
    return __uint_as_float(u);
}

// m16n8k8 tf32 mma: D += A(16x8,row) * B(8x8,col); operands pre-rounded to tf32.
__device__ __forceinline__ void mma_tf32(float* d, const uint32_t* a, const uint32_t* b) {
    asm volatile(
        "mma.sync.aligned.m16n8k8.row.col.f32.tf32.tf32.f32 "
        "{%0,%1,%2,%3}, {%4,%5,%6,%7}, {%8,%9}, {%0,%1,%2,%3};"
        : "+f"(d[0]), "+f"(d[1]), "+f"(d[2]), "+f"(d[3])
        : "r"(a[0]), "r"(a[1]), "r"(a[2]), "r"(a[3]), "r"(b[0]), "r"(b[1]));
}

// ================= K0: init =================
__global__ void vq_init() {
    int i = threadIdx.x;
    if (i == 0) { g_loss = 0.f; g_flagn = 0u; }
    if (i < NK) g_counts[i] = 0u;
}

// ================= K1: tf32 mma GEMM + argmin + margin flag =================
__global__ __launch_bounds__(512, 1) void vq_gemm(
    const float* __restrict__ in, const float* __restrict__ emb,
    float* __restrict__ out)
{
    extern __shared__ float smem[];
    float* sA = smem;                       // TM x ESTR (raw f32 x)
    float* sB = sA + TM * ESTR;             // NK x ESTR (tf32-rounded codebook)
    float* sEn = sB + NK * ESTR;            // NK
    float* sXn = sEn + NK;                  // TM

    const int tid = threadIdx.x;
    const int wid = tid >> 5;
    const int lane = tid & 31;
    const int grp = lane >> 2;              // 0..7
    const int qid = lane & 3;               // 0..3

    const int token0 = blockIdx.x * TM;
    const int b = token0 >> 12;
    const int t0 = token0 & (NT - 1);

    // ---- Stage B, rounded to tf32 (rna) once ----
    {
        const float4* e4 = (const float4*)emb;
        for (int i = tid; i < NK * ND / 4; i += 512) {
            int code = i >> 4, d4 = i & 15;
            float4 v = e4[i];
            float4 r;
            r.x = tf32r(v.x); r.y = tf32r(v.y); r.z = tf32r(v.z); r.w = tf32r(v.w);
            *(float4*)(sB + code * ESTR + 4 * d4) = r;
        }
    }
    // ---- Stage A (raw) + sloppy xn : threads 0..255 ----
    if (tid < TM) {
        const float* xp = in + (size_t)b * ND * NT + (t0 + tid);
        float xn = 0.f;
        float* ar = sA + tid * ESTR;
        #pragma unroll
        for (int d = 0; d < ND; d++) {
            float x = xp[(size_t)d * NT];
            xn = __fmaf_rn(x, x, xn);
            ar[d] = x;
        }
        sXn[tid] = xn;
    } else {
        // ---- sloppy en from original emb : threads 256..511 ----
        for (int k = tid - 256; k < NK; k += 256) {
            const float* e = emb + k * ND;
            float s = 0.f;
            #pragma unroll
            for (int d = 0; d < ND; d++) s = __fmaf_rn(e[d], e[d], s);
            sEn[k] = s;
        }
    }
    __syncthreads();

    // ---- A fragments: tf32-rounded once at load ----
    const int m0 = wid * 16;
    uint32_t ah[8][4];
    #pragma unroll
    for (int kk = 0; kk < 8; kk++) {
        const float* r0 = sA + (m0 + grp) * ESTR + kk * 8;
        const float* r8 = sA + (m0 + grp + 8) * ESTR + kk * 8;
        ah[kk][0] = __float_as_uint(tf32r(r0[qid]));
        ah[kk][1] = __float_as_uint(tf32r(r8[qid]));
        ah[kk][2] = __float_as_uint(tf32r(r0[qid + 4]));
        ah[kk][3] = __float_as_uint(tf32r(r8[qid + 4]));
    }
    const float xnA = sXn[m0 + grp];
    const float xnB = sXn[m0 + grp + 8];

    float bA = 3.4e38f, sA2 = 3.4e38f; int iA = 0;
    float bB = 3.4e38f, sB2 = 3.4e38f; int iB = 0;

    // ---- n-loop: 64 tiles of 8 codes, single mma per kstep (B pre-rounded) ----
    #pragma unroll 1
    for (int n0 = 0; n0 < NK; n0 += 8) {
        float acc[4] = {0.f, 0.f, 0.f, 0.f};
        const float* bp = sB + (n0 + grp) * ESTR;
        #pragma unroll
        for (int kk = 0; kk < 8; kk++) {
            uint32_t bb[2] = { __float_as_uint(bp[kk * 8 + qid]),
                               __float_as_uint(bp[kk * 8 + qid + 4]) };
            mma_tf32(acc, ah[kk], bb);
        }
        const int c0 = n0 + 2 * qid;
        const float en0 = sEn[c0], en1 = sEn[c0 + 1];
        float d0 = (xnA + en0) - 2.f * acc[0];
        float d1 = (xnA + en1) - 2.f * acc[1];
        float d2 = (xnB + en0) - 2.f * acc[2];
        float d3 = (xnB + en1) - 2.f * acc[3];
        if (d0 < bA) { sA2 = bA; bA = d0; iA = c0; } else if (d0 < sA2) sA2 = d0;
        if (d1 < bA) { sA2 = bA; bA = d1; iA = c0 + 1; } else if (d1 < sA2) sA2 = d1;
        if (d2 < bB) { sB2 = bB; bB = d2; iB = c0; } else if (d2 < sB2) sB2 = d2;
        if (d3 < bB) { sB2 = bB; bB = d3; iB = c0 + 1; } else if (d3 < sB2) sB2 = d3;
    }

    // ---- merge across the 4 lanes of each row-group (tie -> lower index) ----
    #pragma unroll
    for (int m = 1; m <= 2; m <<= 1) {
        float ob = __shfl_xor_sync(0xffffffffu, bA, m);
        float os = __shfl_xor_sync(0xffffffffu, sA2, m);
        int   oi = __shfl_xor_sync(0xffffffffu, iA, m);
        if (ob < bA || (ob == bA && oi < iA)) { sA2 = fminf(bA, os); bA = ob; iA = oi; }
        else { sA2 = fminf(sA2, ob); }
        ob = __shfl_xor_sync(0xffffffffu, bB, m);
        os = __shfl_xor_sync(0xffffffffu, sB2, m);
        oi = __shfl_xor_sync(0xffffffffu, iB, m);
        if (ob < bB || (ob == bB && oi < iB)) { sB2 = fminf(bB, os); bB = ob; iB = oi; }
        else { sB2 = fminf(sB2, ob); }
    }

    if (qid == 0) {
        int tokA = token0 + m0 + grp;
        int tokB = tokA + 8;
        out[IDX_OFF + (size_t)tokA] = (float)iA;
        out[IDX_OFF + (size_t)tokB] = (float)iB;
        if (!(sA2 - bA > THETA)) {          // tiny margin (or NaN) -> exact path
            unsigned p = atomicAdd(&g_flagn, 1u);
            g_flags[p] = tokA;
        }
        if (!(sB2 - bB > THETA)) {
            unsigned p = atomicAdd(&g_flagn, 1u);
            g_flags[p] = tokB;
        }
    }
}

// ======== K2: exact frozen recompute, one flagged token per thread, smem codebook ======
__global__ __launch_bounds__(512, 1) void vq_cleanup(
    const float* __restrict__ in, const float* __restrict__ emb,
    float* __restrict__ out)
{
    extern __shared__ float smem[];
    float* sE = smem;                 // NK x ESTR (raw f32)
    float* sEn = sE + NK * ESTR;      // NK (FROZEN norms)

    const int tid = threadIdx.x;
    const int wid = tid >> 5;
    const int lane = tid & 31;

    // Stage codebook (padded stride)
    {
        const float4* e4 = (const float4*)emb;
        for (int i = tid; i < NK * ND / 4; i += 512) {
            int code = i >> 4, d4 = i & 15;
            float4 v = e4[i];
            *(float4*)(sE + code * ESTR + 4 * d4) = v;
        }
    }
    // FROZEN en: no-fma products, lane sums {l, l+32}, shfl tree 16..1
    for (int k = wid; k < NK; k += 16) {
        const float* e = emb + k * ND;
        float a = __fmul_rn(e[lane], e[lane]);
        float c = __fmul_rn(e[lane + 32], e[lane + 32]);
        float acc = __fadd_rn(a, c);
        #pragma unroll
        for (int off = 16; off; off >>= 1)
            acc = __fadd_rn(acc, __shfl_down_sync(0xffffffffu, acc, off));
        if (lane == 0) sEn[k] = acc;
    }
    __syncthreads();

    const unsigned count = g_flagn;

    for (unsigned fi = blockIdx.x * 512 + tid; fi < count; fi += gridDim.x * 512) {
        const int token = g_flags[fi];
        const int b = token >> 12, t = token & (NT - 1);

        const float* xp = in + (size_t)b * ND * NT + t;
        float x[ND];
        #pragma unroll
        for (int d = 0; d < ND; d++) x[d] = xp[(size_t)d * NT];

        // FROZEN xn: sequential ascending, no fma contraction
        float xn = 0.f;
        #pragma unroll
        for (int d = 0; d < ND; d++) xn = __fadd_rn(xn, __fmul_rn(x[d], x[d]));

        // FROZEN argmin: per-code sequential ascending fma chain, 4 codes ILP,
        // uniform LDS.128, combine fl(fl(xn+en) + fl(-2*dot)), first-min.
        float best = 3.402823466e38f;
        int bidx = 0;
        for (int k0 = 0; k0 < NK; k0 += 4) {
            const float4* e0 = (const float4*)(sE + (k0 + 0) * ESTR);
            const float4* e1 = (const float4*)(sE + (k0 + 1) * ESTR);
            const float4* e2 = (const float4*)(sE + (k0 + 2) * ESTR);
            const float4* e3 = (const float4*)(sE + (k0 + 3) * ESTR);
            float a0 = 0.f, a1 = 0.f, a2 = 0.f, a3 = 0.f;
            #pragma unroll
            for (int j = 0; j < ND / 4; j++) {
                float4 v0 = e0[j], v1 = e1[j], v2 = e2[j], v3 = e3[j];
                a0 = __fmaf_rn(x[4*j+0], v0.x, a0);
                a1 = __fmaf_rn(x[4*j+0], v1.x, a1);
                a2 = __fmaf_rn(x[4*j+0], v2.x, a2);
                a3 = __fmaf_rn(x[4*j+0], v3.x, a3);
                a0 = __fmaf_rn(x[4*j+1], v0.y, a0);
                a1 = __fmaf_rn(x[4*j+1], v1.y, a1);
                a2 = __fmaf_rn(x[4*j+1], v2.y, a2);
                a3 = __fmaf_rn(x[4*j+1], v3.y, a3);
                a0 = __fmaf_rn(x[4*j+2], v0.z, a0);
                a1 = __fmaf_rn(x[4*j+2], v1.z, a1);
                a2 = __fmaf_rn(x[4*j+2], v2.z, a2);
                a3 = __fmaf_rn(x[4*j+2], v3.z, a3);
                a0 = __fmaf_rn(x[4*j+3], v0.w, a0);
                a1 = __fmaf_rn(x[4*j+3], v1.w, a1);
                a2 = __fmaf_rn(x[4*j+3], v2.w, a2);
                a3 = __fmaf_rn(x[4*j+3], v3.w, a3);
            }
            float d0 = __fadd_rn(__fadd_rn(xn, sEn[k0 + 0]), __fmul_rn(-2.f, a0));
            float d1 = __fadd_rn(__fadd_rn(xn, sEn[k0 + 1]), __fmul_rn(-2.f, a1));
            float d2 = __fadd_rn(__fadd_rn(xn, sEn[k0 + 2]), __fmul_rn(-2.f, a2));
            float d3 = __fadd_rn(__fadd_rn(xn, sEn[k0 + 3]), __fmul_rn(-2.f, a3));
            if (d0 < best) { best = d0; bidx = k0 + 0; }
            if (d1 < best) { best = d1; bidx = k0 + 1; }
            if (d2 < best) { best = d2; bidx = k0 + 2; }
            if (d3 < best) { best = d3; bidx = k0 + 3; }
        }
        out[IDX_OFF + (size_t)token] = (float)bidx;
    }
}

// ================= K3: gather + loss + histogram (from final indices) =================
__global__ __launch_bounds__(512, 1) void vq_gather(
    const float* __restrict__ in, const float* __restrict__ emb,
    float* __restrict__ out)
{
    __shared__ unsigned int sCount[NK];
    __shared__ float sLoss;
    const int tid = threadIdx.x;
    if (tid == 0) sLoss = 0.f;
    if (tid < NK) sCount[tid] = 0u;
    __syncthreads();

    const int token = blockIdx.x * 512 + tid;
    const int b = token >> 12, t = token & (NT - 1);
    const int k = (int)out[IDX_OFF + (size_t)token];

    atomicAdd(&sCount[k], 1u);

    const float* xp = in + (size_t)b * ND * NT + t;
    const float4* eb4 = (const float4*)(emb + k * ND);
    float* qp = out + Q_OFF + (size_t)b * ND * NT + t;
    float lsum = 0.f;
    #pragma unroll
    for (int j = 0; j < ND / 4; j++) {
        float4 v = eb4[j];
        float x0 = xp[(size_t)(4 * j + 0) * NT];
        float x1 = xp[(size_t)(4 * j + 1) * NT];
        float x2 = xp[(size_t)(4 * j + 2) * NT];
        float x3 = xp[(size_t)(4 * j + 3) * NT];
        qp[(size_t)(4 * j + 0) * NT] = v.x;
        qp[(size_t)(4 * j + 1) * NT] = v.y;
        qp[(size_t)(4 * j + 2) * NT] = v.z;
        qp[(size_t)(4 * j + 3) * NT] = v.w;
        float t0 = v.x - x0, t1 = v.y - x1, t2 = v.z - x2, t3 = v.w - x3;
        lsum = __fmaf_rn(t0, t0, lsum);
        lsum = __fmaf_rn(t1, t1, lsum);
        lsum = __fmaf_rn(t2, t2, lsum);
        lsum = __fmaf_rn(t3, t3, lsum);
    }
    #pragma unroll
    for (int off = 16; off; off >>= 1)
        lsum += __shfl_down_sync(0xffffffffu, lsum, off);
    if ((tid & 31) == 0) atomicAdd(&sLoss, lsum);
    __syncthreads();
    if (tid == 0) atomicAdd(&g_loss, sLoss);
    if (tid < NK) {
        unsigned c = sCount[tid];
        if (c) atomicAdd(&g_counts[tid], c);
    }
}

// ================= K4: finalize =================
__global__ void vq_final(float* __restrict__ out) {
    __shared__ float red[32];
    int tid = threadIdx.x;
    if (tid < 32) red[tid] = 0.f;
    __syncthreads();
    unsigned c = g_counts[tid];
    float p = (float)c / (float)NTOK;
    float term = p * logf(p + 1e-10f);
    #pragma unroll
    for (int off = 16; off; off >>= 1)
        term += __shfl_down_sync(0xffffffffu, term, off);
    if ((tid & 31) == 0) red[tid >> 5] = term;
    __syncthreads();
    if (tid < 32) {
        float v = red[tid];
        #pragma unroll
        for (int off = 16; off; off >>= 1)
            v += __shfl_down_sync(0xffffffffu, v, off);
        if (tid == 0) {
            out[PERP_OFF] = expf(-v);
            out[0] = 0.25f * g_loss / (float)((size_t)NTOK * ND);
        }
    }
}

extern "C" void kernel_launch(void* const* d_in, const int* in_sizes, int n_in,
                              void* d_out, int out_size) {
    const float* in  = (const float*)d_in[0];   // [32, 64, 4096]
    const float* emb = (const float*)d_in[1];   // [512, 64]
    float* out = (float*)d_out;

    size_t smem_g = (size_t)(TM * ESTR + NK * ESTR + NK + TM) * sizeof(float);
    size_t smem_c = (size_t)(NK * ESTR + NK) * sizeof(float);
    cudaFuncSetAttribute(vq_gemm, cudaFuncAttributeMaxDynamicSharedMemorySize, (int)smem_g);
    cudaFuncSetAttribute(vq_cleanup, cudaFuncAttributeMaxDynamicSharedMemorySize, (int)smem_c);

    vq_init<<<1, 512>>>();
    vq_gemm<<<NTILE, 512, smem_g>>>(in, emb, out);
    vq_cleanup<<<148, 512, smem_c>>>(in, emb, out);
    vq_gather<<<NTOK / 512, 512>>>(in, emb, out);
    vq_final<<<1, 512>>>(out);
}

// round 13
// speedup vs baseline: 4.5999x; 1.3020x over previous
#include <cuda_runtime.h>
#include <math.h>
#include <stdint.h>

// Problem constants
#define NB 32
#define ND 64
#define NT 4096
#define NK 512
#define NTOK (NB * NT)          // 131072 tokens
#define TM 128                  // tokens per tile
#define NTILES (NTOK / TM)      // 1024 tiles
#define NCTA 148
#define ESTR 68                 // smem row stride (floats)

// Output layout (float32, reference tuple flattened in order)
#define Q_OFF     ((size_t)1)
#define PERP_OFF  ((size_t)1 + (size_t)NB * ND * NT)
#define IDX_OFF   (PERP_OFF + 1)

// Margin threshold: tf32-rna distance error rms ~1e-3 (R3 anchor), key masking
// slop ~0.008; THETA=0.05 safely flags every possibly-flipped token.
#define THETA 0.05f

__device__ float g_loss;
__device__ unsigned int g_counts[NK];
__device__ unsigned int g_flagn;
__device__ int g_flags[NTOK];

__device__ __forceinline__ float tf32r(float v) {
    uint32_t u;
    asm("cvt.rna.tf32.f32 %0, %1;" : "=r"(u) : "f"(v));
    return __uint_as_float(u);
}
// order-preserving uint encoding of float (handles negatives), idx in low 9 bits
__device__ __forceinline__ uint32_t distkey(float d, int col) {
    uint32_t u = __float_as_uint(d);
    u ^= (uint32_t)((int32_t)u >> 31) | 0x80000000u;
    return (u & 0xFFFFFE00u) | (uint32_t)col;
}
__device__ __forceinline__ float keyinv(uint32_t k) {
    uint32_t u = k & 0xFFFFFE00u;
    u = (u & 0x80000000u) ? (u ^ 0x80000000u) : ~u;
    return __uint_as_float(u);
}

// m16n8k8 tf32 mma: D += A(16x8,row) * B(8x8,col); operands pre-rounded tf32.
__device__ __forceinline__ void mma_tf32(float* d, const uint32_t* a, const uint32_t* b) {
    asm volatile(
        "mma.sync.aligned.m16n8k8.row.col.f32.tf32.tf32.f32 "
        "{%0,%1,%2,%3}, {%4,%5,%6,%7}, {%8,%9}, {%0,%1,%2,%3};"
        : "+f"(d[0]), "+f"(d[1]), "+f"(d[2]), "+f"(d[3])
        : "r"(a[0]), "r"(a[1]), "r"(a[2]), "r"(a[3]), "r"(b[0]), "r"(b[1]));
}

// ================= K0: init =================
__global__ void vq_init() {
    int i = threadIdx.x;
    if (i == 0) { g_loss = 0.f; g_flagn = 0u; }
    if (i < NK) g_counts[i] = 0u;
}

// ========== K1: persistent tf32 GEMM + predicate-free argmin + margin flag ==========
__global__ __launch_bounds__(512, 1) void vq_gemm(
    const float* __restrict__ in, const float* __restrict__ emb,
    float* __restrict__ out)
{
    extern __shared__ float smem[];
    float* sB   = smem;                        // NK x ESTR (tf32-rounded)
    float* sA   = sB + NK * ESTR;              // TM x ESTR
    float* sEn  = sA + TM * ESTR;              // NK
    float* sXnP = sEn + NK;                    // 512 partials
    float* sXn  = sXnP + 512;                  // TM
    uint32_t* sM1 = (uint32_t*)(sXn + TM);     // TM (half1 best key)
    uint32_t* sM2 = sM1 + TM;                  // TM (half1 second key)

    const int tid = threadIdx.x;
    const int wid = tid >> 5;
    const int lane = tid & 31;
    const int grp = lane >> 2;                 // 0..7
    const int qid = lane & 3;                  // 0..3
    const int h   = wid >> 3;                  // n-half
    const int mb  = (wid & 7) * 16;            // m-block base row

    // ---- ONE-TIME staging: B (tf32-rounded) + en (coalesced warp-tree) ----
    {
        const float4* e4 = (const float4*)emb;
        for (int i = tid; i < NK * ND / 4; i += 512) {
            int code = i >> 4, d4 = i & 15;
            float4 v = e4[i];
            float4 r;
            r.x = tf32r(v.x); r.y = tf32r(v.y); r.z = tf32r(v.z); r.w = tf32r(v.w);
            *(float4*)(sB + code * ESTR + 4 * d4) = r;
        }
    }
    for (int k = wid; k < NK; k += 16) {       // coalesced: lane indexes d
        const float* e = emb + k * ND;
        float acc = __fmaf_rn(e[lane], e[lane], __fmul_rn(e[lane + 32], e[lane + 32]));
        #pragma unroll
        for (int off = 16; off; off >>= 1)
            acc += __shfl_down_sync(0xffffffffu, acc, off);
        if (lane == 0) sEn[k] = acc;
    }
    __syncthreads();

    // ---- persistent tile loop ----
    for (int tile = blockIdx.x; tile < NTILES; tile += gridDim.x) {
        const int token0 = tile * TM;
        const int b = token0 >> 12;
        const int t0 = token0 & (NT - 1);

        // A staging: 512 threads, token = tid&127, quarter of d each (coalesced)
        {
            const int tok = tid & 127, part = tid >> 7;   // part 0..3
            const float* xp = in + (size_t)b * ND * NT + (t0 + tok);
            float p = 0.f;
            float* ar = sA + tok * ESTR + part * 16;
            #pragma unroll
            for (int i = 0; i < 16; i++) {
                float x = xp[(size_t)(part * 16 + i) * NT];
                ar[i] = x;
                p = __fmaf_rn(x, x, p);
            }
            sXnP[tok * 4 + part] = p;
        }
        __syncthreads();
        if (tid < TM) {
            const float* p = sXnP + tid * 4;
            sXn[tid] = (p[0] + p[1]) + (p[2] + p[3]);
        }
        __syncthreads();

        // A fragments (tf32-rounded once)
        uint32_t ah[8][4];
        #pragma unroll
        for (int kk = 0; kk < 8; kk++) {
            const float* r0 = sA + (mb + grp) * ESTR + kk * 8;
            const float* r8 = sA + (mb + grp + 8) * ESTR + kk * 8;
            ah[kk][0] = __float_as_uint(tf32r(r0[qid]));
            ah[kk][1] = __float_as_uint(tf32r(r8[qid]));
            ah[kk][2] = __float_as_uint(tf32r(r0[qid + 4]));
            ah[kk][3] = __float_as_uint(tf32r(r8[qid + 4]));
        }
        const float xnA = sXn[mb + grp];
        const float xnB = sXn[mb + grp + 8];

        uint32_t m1A = 0xFFFFFFFFu, m2A = 0xFFFFFFFFu;
        uint32_t m1B = 0xFFFFFFFFu, m2B = 0xFFFFFFFFu;

        // n-loop over this warp's half: 32 tiles of 8 codes
        #pragma unroll 1
        for (int nt = 0; nt < 32; nt++) {
            const int n0 = h * 256 + nt * 8;
            float acc[4] = {0.f, 0.f, 0.f, 0.f};
            const float* bp = sB + (n0 + grp) * ESTR;
            #pragma unroll
            for (int kk = 0; kk < 8; kk++) {
                uint32_t bb[2] = { __float_as_uint(bp[kk * 8 + qid]),
                                   __float_as_uint(bp[kk * 8 + qid + 4]) };
                mma_tf32(acc, ah[kk], bb);
            }
            const int c0 = n0 + 2 * qid;
            const float sa0 = xnA + sEn[c0];
            const float sa1 = xnA + sEn[c0 + 1];
            const float sb0 = xnB + sEn[c0];
            const float sb1 = xnB + sEn[c0 + 1];
            uint32_t k0 = distkey(__fmaf_rn(-2.f, acc[0], sa0), c0);
            uint32_t k1 = distkey(__fmaf_rn(-2.f, acc[1], sa1), c0 + 1);
            uint32_t k2 = distkey(__fmaf_rn(-2.f, acc[2], sb0), c0);
            uint32_t k3 = distkey(__fmaf_rn(-2.f, acc[3], sb1), c0 + 1);
            // predicate-free best/second (umin/umax only)
            uint32_t hi;
            hi = max(m1A, k0); m1A = min(m1A, k0); m2A = min(m2A, hi);
            hi = max(m1A, k1); m1A = min(m1A, k1); m2A = min(m2A, hi);
            hi = max(m1B, k2); m1B = min(m1B, k2); m2B = min(m2B, hi);
            hi = max(m1B, k3); m1B = min(m1B, k3); m2B = min(m2B, hi);
        }

        // merge across the 4 lanes of each row-group
        #pragma unroll
        for (int m = 1; m <= 2; m <<= 1) {
            uint32_t o1 = __shfl_xor_sync(0xffffffffu, m1A, m);
            uint32_t o2 = __shfl_xor_sync(0xffffffffu, m2A, m);
            uint32_t hi = max(m1A, o1);
            m1A = min(m1A, o1);
            m2A = min(min(m2A, o2), hi);
            o1 = __shfl_xor_sync(0xffffffffu, m1B, m);
            o2 = __shfl_xor_sync(0xffffffffu, m2B, m);
            hi = max(m1B, o1);
            m1B = min(m1B, o1);
            m2B = min(min(m2B, o2), hi);
        }

        // half1 publishes, half0 merges + writes idx + flags
        if (h == 1 && qid == 0) {
            sM1[mb + grp] = m1A; sM2[mb + grp] = m2A;
            sM1[mb + grp + 8] = m1B; sM2[mb + grp + 8] = m2B;
        }
        __syncthreads();
        if (h == 0 && qid == 0) {
            #pragma unroll
            for (int half = 0; half < 2; half++) {
                const int row = mb + grp + 8 * half;
                uint32_t m1 = half ? m1B : m1A;
                uint32_t m2 = half ? m2B : m2A;
                uint32_t o1 = sM1[row], o2 = sM2[row];
                uint32_t hi = max(m1, o1);
                m1 = min(m1, o1);
                m2 = min(min(m2, o2), hi);
                const int gtok = token0 + row;
                out[IDX_OFF + (size_t)gtok] = (float)(m1 & 0x1FFu);
                float margin = keyinv(m2) - keyinv(m1);
                if (!(margin > THETA)) {
                    unsigned p = atomicAdd(&g_flagn, 1u);
                    g_flags[p] = gtok;
                }
            }
        }
        __syncthreads();   // protect sA / sM before next tile
    }
}

// ======== K2: exact frozen recompute, one flagged token per thread, smem codebook ======
__global__ __launch_bounds__(512, 1) void vq_cleanup(
    const float* __restrict__ in, const float* __restrict__ emb,
    float* __restrict__ out)
{
    extern __shared__ float smem[];
    float* sE = smem;                 // NK x ESTR (raw f32)
    float* sEn = sE + NK * ESTR;      // NK (FROZEN norms)

    const int tid = threadIdx.x;
    const int wid = tid >> 5;
    const int lane = tid & 31;

    {
        const float4* e4 = (const float4*)emb;
        for (int i = tid; i < NK * ND / 4; i += 512) {
            int code = i >> 4, d4 = i & 15;
            float4 v = e4[i];
            *(float4*)(sE + code * ESTR + 4 * d4) = v;
        }
    }
    // FROZEN en: no-fma products, lane sums {l, l+32}, shfl tree 16..1
    for (int k = wid; k < NK; k += 16) {
        const float* e = emb + k * ND;
        float a = __fmul_rn(e[lane], e[lane]);
        float c = __fmul_rn(e[lane + 32], e[lane + 32]);
        float acc = __fadd_rn(a, c);
        #pragma unroll
        for (int off = 16; off; off >>= 1)
            acc = __fadd_rn(acc, __shfl_down_sync(0xffffffffu, acc, off));
        if (lane == 0) sEn[k] = acc;
    }
    __syncthreads();

    const unsigned count = g_flagn;

    for (unsigned fi = blockIdx.x * 512 + tid; fi < count; fi += gridDim.x * 512) {
        const int token = g_flags[fi];
        const int b = token >> 12, t = token & (NT - 1);

        const float* xp = in + (size_t)b * ND * NT + t;
        float x[ND];
        #pragma unroll
        for (int d = 0; d < ND; d++) x[d] = xp[(size_t)d * NT];

        // FROZEN xn: sequential ascending, no fma contraction
        float xn = 0.f;
        #pragma unroll
        for (int d = 0; d < ND; d++) xn = __fadd_rn(xn, __fmul_rn(x[d], x[d]));

        // FROZEN argmin: sequential ascending fma dot per code, 4 codes ILP,
        // combine fl(fl(xn+en) + fl(-2*dot)), strict < first-min.
        float best = 3.402823466e38f;
        int bidx = 0;
        for (int k0 = 0; k0 < NK; k0 += 4) {
            const float4* e0 = (const float4*)(sE + (k0 + 0) * ESTR);
            const float4* e1 = (const float4*)(sE + (k0 + 1) * ESTR);
            const float4* e2 = (const float4*)(sE + (k0 + 2) * ESTR);
            const float4* e3 = (const float4*)(sE + (k0 + 3) * ESTR);
            float a0 = 0.f, a1 = 0.f, a2 = 0.f, a3 = 0.f;
            #pragma unroll
            for (int j = 0; j < ND / 4; j++) {
                float4 v0 = e0[j], v1 = e1[j], v2 = e2[j], v3 = e3[j];
                a0 = __fmaf_rn(x[4*j+0], v0.x, a0);
                a1 = __fmaf_rn(x[4*j+0], v1.x, a1);
                a2 = __fmaf_rn(x[4*j+0], v2.x, a2);
                a3 = __fmaf_rn(x[4*j+0], v3.x, a3);
                a0 = __fmaf_rn(x[4*j+1], v0.y, a0);
                a1 = __fmaf_rn(x[4*j+1], v1.y, a1);
                a2 = __fmaf_rn(x[4*j+1], v2.y, a2);
                a3 = __fmaf_rn(x[4*j+1], v3.y, a3);
                a0 = __fmaf_rn(x[4*j+2], v0.z, a0);
                a1 = __fmaf_rn(x[4*j+2], v1.z, a1);
                a2 = __fmaf_rn(x[4*j+2], v2.z, a2);
                a3 = __fmaf_rn(x[4*j+2], v3.z, a3);
                a0 = __fmaf_rn(x[4*j+3], v0.w, a0);
                a1 = __fmaf_rn(x[4*j+3], v1.w, a1);
                a2 = __fmaf_rn(x[4*j+3], v2.w, a2);
                a3 = __fmaf_rn(x[4*j+3], v3.w, a3);
            }
            float d0 = __fadd_rn(__fadd_rn(xn, sEn[k0 + 0]), __fmul_rn(-2.f, a0));
            float d1 = __fadd_rn(__fadd_rn(xn, sEn[k0 + 1]), __fmul_rn(-2.f, a1));
            float d2 = __fadd_rn(__fadd_rn(xn, sEn[k0 + 2]), __fmul_rn(-2.f, a2));
            float d3 = __fadd_rn(__fadd_rn(xn, sEn[k0 + 3]), __fmul_rn(-2.f, a3));
            if (d0 < best) { best = d0; bidx = k0 + 0; }
            if (d1 < best) { best = d1; bidx = k0 + 1; }
            if (d2 < best) { best = d2; bidx = k0 + 2; }
            if (d3 < best) { best = d3; bidx = k0 + 3; }
        }
        out[IDX_OFF + (size_t)token] = (float)bidx;
    }
}

// ================= K3: gather + loss + histogram (from final indices) =================
__global__ __launch_bounds__(512, 1) void vq_gather(
    const float* __restrict__ in, const float* __restrict__ emb,
    float* __restrict__ out)
{
    __shared__ unsigned int sCount[NK];
    __shared__ float sLoss;
    const int tid = threadIdx.x;
    if (tid == 0) sLoss = 0.f;
    if (tid < NK) sCount[tid] = 0u;
    __syncthreads();

    const int token = blockIdx.x * 512 + tid;
    const int b = token >> 12, t = token & (NT - 1);
    const int k = (int)out[IDX_OFF + (size_t)token];

    atomicAdd(&sCount[k], 1u);

    const float* xp = in + (size_t)b * ND * NT + t;
    const float4* eb4 = (const float4*)(emb + k * ND);
    float* qp = out + Q_OFF + (size_t)b * ND * NT + t;
    float lsum = 0.f;
    #pragma unroll
    for (int j = 0; j < ND / 4; j++) {
        float4 v = eb4[j];
        float x0 = xp[(size_t)(4 * j + 0) * NT];
        float x1 = xp[(size_t)(4 * j + 1) * NT];
        float x2 = xp[(size_t)(4 * j + 2) * NT];
        float x3 = xp[(size_t)(4 * j + 3) * NT];
        qp[(size_t)(4 * j + 0) * NT] = v.x;
        qp[(size_t)(4 * j + 1) * NT] = v.y;
        qp[(size_t)(4 * j + 2) * NT] = v.z;
        qp[(size_t)(4 * j + 3) * NT] = v.w;
        float t0 = v.x - x0, t1 = v.y - x1, t2 = v.z - x2, t3 = v.w - x3;
        lsum = __fmaf_rn(t0, t0, lsum);
        lsum = __fmaf_rn(t1, t1, lsum);
        lsum = __fmaf_rn(t2, t2, lsum);
        lsum = __fmaf_rn(t3, t3, lsum);
    }
    #pragma unroll
    for (int off = 16; off; off >>= 1)
        lsum += __shfl_down_sync(0xffffffffu, lsum, off);
    if ((tid & 31) == 0) atomicAdd(&sLoss, lsum);
    __syncthreads();
    if (tid == 0) atomicAdd(&g_loss, sLoss);
    if (tid < NK) {
        unsigned c = sCount[tid];
        if (c) atomicAdd(&g_counts[tid], c);
    }
}

// ================= K4: finalize =================
__global__ void vq_final(float* __restrict__ out) {
    __shared__ float red[32];
    int tid = threadIdx.x;
    if (tid < 32) red[tid] = 0.f;
    __syncthreads();
    unsigned c = g_counts[tid];
    float p = (float)c / (float)NTOK;
    float term = p * logf(p + 1e-10f);
    #pragma unroll
    for (int off = 16; off; off >>= 1)
        term += __shfl_down_sync(0xffffffffu, term, off);
    if ((tid & 31) == 0) red[tid >> 5] = term;
    __syncthreads();
    if (tid < 32) {
        float v = red[tid];
        #pragma unroll
        for (int off = 16; off; off >>= 1)
            v += __shfl_down_sync(0xffffffffu, v, off);
        if (tid == 0) {
            out[PERP_OFF] = expf(-v);
            out[0] = 0.25f * g_loss / (float)((size_t)NTOK * ND);
        }
    }
}

extern "C" void kernel_launch(void* const* d_in, const int* in_sizes, int n_in,
                              void* d_out, int out_size) {
    const float* in  = (const float*)d_in[0];   // [32, 64, 4096]
    const float* emb = (const float*)d_in[1];   // [512, 64]
    float* out = (float*)d_out;

    size_t smem_g = (size_t)(NK * ESTR + TM * ESTR + NK + 512 + TM + 2 * TM) * sizeof(float);
    size_t smem_c = (size_t)(NK * ESTR + NK) * sizeof(float);
    cudaFuncSetAttribute(vq_gemm, cudaFuncAttributeMaxDynamicSharedMemorySize, (int)smem_g);
    cudaFuncSetAttribute(vq_cleanup, cudaFuncAttributeMaxDynamicSharedMemorySize, (int)smem_c);

    vq_init<<<1, 512>>>();
    vq_gemm<<<NCTA, 512, smem_g>>>(in, emb, out);
    vq_cleanup<<<NCTA, 512, smem_c>>>(in, emb, out);
    vq_gather<<<NTOK / 512, 512>>>(in, emb, out);
    vq_final<<<1, 512>>>(out);
}

// round 14
// speedup vs baseline: 4.7029x; 1.0224x over previous
#include <cuda_runtime.h>
#include <math.h>
#include <stdint.h>

// Problem constants
#define NB 32
#define ND 64
#define NT 4096
#define NK 512
#define NTOK (NB * NT)          // 131072 tokens
#define TM 128                  // tokens per tile
#define NTILES (NTOK / TM)      // 1024 tiles
#define NCTA 148
#define ESTR 68                 // smem row stride (floats)

// Output layout (float32, reference tuple flattened in order)
#define Q_OFF     ((size_t)1)
#define PERP_OFF  ((size_t)1 + (size_t)NB * ND * NT)
#define IDX_OFF   (PERP_OFF + 1)

// Margin threshold: tf32-rna distance error rms ~1e-3 (R3 anchor) + key masking
// slop ~0.008 + chain-split reassociation ~1e-5; THETA=0.05 covers all.
#define THETA 0.05f

__device__ float g_loss;
__device__ unsigned int g_counts[NK];
__device__ unsigned int g_flagn;
__device__ int g_flags[NTOK];

__device__ __forceinline__ float tf32r(float v) {
    uint32_t u;
    asm("cvt.rna.tf32.f32 %0, %1;" : "=r"(u) : "f"(v));
    return __uint_as_float(u);
}
// order-preserving uint encoding of float (handles negatives), idx in low 9 bits
__device__ __forceinline__ uint32_t distkey(float d, int col) {
    uint32_t u = __float_as_uint(d);
    u ^= (uint32_t)((int32_t)u >> 31) | 0x80000000u;
    return (u & 0xFFFFFE00u) | (uint32_t)col;
}
__device__ __forceinline__ float keyinv(uint32_t k) {
    uint32_t u = k & 0xFFFFFE00u;
    u = (u & 0x80000000u) ? (u ^ 0x80000000u) : ~u;
    return __uint_as_float(u);
}

// m16n8k8 tf32 mma: D += A(16x8,row) * B(8x8,col); operands pre-rounded tf32.
__device__ __forceinline__ void mma_tf32(float* d, const uint32_t* a, const uint32_t* b) {
    asm volatile(
        "mma.sync.aligned.m16n8k8.row.col.f32.tf32.tf32.f32 "
        "{%0,%1,%2,%3}, {%4,%5,%6,%7}, {%8,%9}, {%0,%1,%2,%3};"
        : "+f"(d[0]), "+f"(d[1]), "+f"(d[2]), "+f"(d[3])
        : "r"(a[0]), "r"(a[1]), "r"(a[2]), "r"(a[3]), "r"(b[0]), "r"(b[1]));
}

// ================= K0: init =================
__global__ void vq_init() {
    int i = threadIdx.x;
    if (i == 0) { g_loss = 0.f; g_flagn = 0u; }
    if (i < NK) g_counts[i] = 0u;
}

// ========== K1: persistent tf32 GEMM, 4 concurrent mma chains, argmin + flag ==========
__global__ __launch_bounds__(512, 1) void vq_gemm(
    const float* __restrict__ in, const float* __restrict__ emb,
    float* __restrict__ out)
{
    extern __shared__ float smem[];
    // Fragment-packed B: [ntile(64)][kk(8)][lane(32)] float2
    //   value = { tf32(e[ntile*8 + lane>>2][kk*8 + (lane&3)]),
    //             tf32(e[ntile*8 + lane>>2][kk*8 + (lane&3) + 4]) }
    float2* sBf = (float2*)smem;               // 16384 float2 = 128 KB
    float* sA   = (float*)(sBf + 64 * 8 * 32); // TM x ESTR
    float* sEn  = sA + TM * ESTR;              // NK
    float* sXnP = sEn + NK;                    // 512 partials
    float* sXn  = sXnP + 512;                  // TM
    uint32_t* sM1 = (uint32_t*)(sXn + TM);     // TM (half1 best key)
    uint32_t* sM2 = sM1 + TM;                  // TM (half1 second key)

    const int tid = threadIdx.x;
    const int wid = tid >> 5;
    const int lane = tid & 31;
    const int grp = lane >> 2;                 // 0..7
    const int qid = lane & 3;                  // 0..3
    const int h   = wid >> 3;                  // n-half (ntiles [h*32, h*32+32))
    const int mb  = (wid & 7) * 16;            // m-block base row

    // ---- ONE-TIME staging: fragment-packed tf32 B + en (coalesced warp-tree) ----
    for (int i = tid; i < 64 * 8 * 32; i += 512) {
        int ntile = i >> 8, kk = (i >> 5) & 7, ln = i & 31;
        int code = ntile * 8 + (ln >> 2), d = kk * 8 + (ln & 3);
        sBf[i] = make_float2(tf32r(emb[code * ND + d]),
                             tf32r(emb[code * ND + d + 4]));
    }
    for (int k = wid; k < NK; k += 16) {       // coalesced: lane indexes d
        const float* e = emb + k * ND;
        float acc = __fmaf_rn(e[lane], e[lane], __fmul_rn(e[lane + 32], e[lane + 32]));
        #pragma unroll
        for (int off = 16; off; off >>= 1)
            acc += __shfl_down_sync(0xffffffffu, acc, off);
        if (lane == 0) sEn[k] = acc;
    }
    __syncthreads();

    // ---- persistent tile loop ----
    for (int tile = blockIdx.x; tile < NTILES; tile += gridDim.x) {
        const int token0 = tile * TM;
        const int b = token0 >> 12;
        const int t0 = token0 & (NT - 1);

        // A staging: token = tid&127, quarter of d each (coalesced)
        {
            const int tok = tid & 127, part = tid >> 7;
            const float* xp = in + (size_t)b * ND * NT + (t0 + tok);
            float p = 0.f;
            float* ar = sA + tok * ESTR + part * 16;
            #pragma unroll
            for (int i = 0; i < 16; i++) {
                float x = xp[(size_t)(part * 16 + i) * NT];
                ar[i] = x;
                p = __fmaf_rn(x, x, p);
            }
            sXnP[tok * 4 + part] = p;
        }
        __syncthreads();
        if (tid < TM) {
            const float* p = sXnP + tid * 4;
            sXn[tid] = (p[0] + p[1]) + (p[2] + p[3]);
        }
        __syncthreads();

        // A fragments (tf32-rounded once)
        uint32_t ah[8][4];
        #pragma unroll
        for (int kk = 0; kk < 8; kk++) {
            const float* r0 = sA + (mb + grp) * ESTR + kk * 8;
            const float* r8 = sA + (mb + grp + 8) * ESTR + kk * 8;
            ah[kk][0] = __float_as_uint(tf32r(r0[qid]));
            ah[kk][1] = __float_as_uint(tf32r(r8[qid]));
            ah[kk][2] = __float_as_uint(tf32r(r0[qid + 4]));
            ah[kk][3] = __float_as_uint(tf32r(r8[qid + 4]));
        }
        const float xnA = sXn[mb + grp];
        const float xnB = sXn[mb + grp + 8];

        uint32_t m1A = 0xFFFFFFFFu, m2A = 0xFFFFFFFFu;
        uint32_t m1B = 0xFFFFFFFFu, m2B = 0xFFFFFFFFu;

        // n-loop: 2 n-tiles per iteration x 2 kk-chains = 4 independent mma chains
        #pragma unroll 1
        for (int nt = 0; nt < 32; nt += 2) {
            const int ntile = h * 32 + nt;
            const float2* f0 = sBf + ntile * 256 + lane;
            const float2* f1 = f0 + 256;
            float p0[4] = {0.f, 0.f, 0.f, 0.f};   // n-tile0, kk 0-3
            float p1[4] = {0.f, 0.f, 0.f, 0.f};   // n-tile0, kk 4-7
            float q0[4] = {0.f, 0.f, 0.f, 0.f};   // n-tile1, kk 0-3
            float q1[4] = {0.f, 0.f, 0.f, 0.f};   // n-tile1, kk 4-7
            #pragma unroll
            for (int kk = 0; kk < 4; kk++) {
                float2 b0 = f0[kk * 32];
                float2 b1 = f1[kk * 32];
                float2 b2 = f0[(kk + 4) * 32];
                float2 b3 = f1[(kk + 4) * 32];
                mma_tf32(p0, ah[kk],     (const uint32_t*)&b0);
                mma_tf32(q0, ah[kk],     (const uint32_t*)&b1);
                mma_tf32(p1, ah[kk + 4], (const uint32_t*)&b2);
                mma_tf32(q1, ah[kk + 4], (const uint32_t*)&b3);
            }
            #pragma unroll
            for (int half = 0; half < 2; half++) {
                const float* u = half ? q0 : p0;
                const float* v = half ? q1 : p1;
                const int c0 = (ntile + half) * 8 + 2 * qid;
                const float en0 = sEn[c0], en1 = sEn[c0 + 1];
                uint32_t k0 = distkey(__fmaf_rn(-2.f, u[0] + v[0], xnA + en0), c0);
                uint32_t k1 = distkey(__fmaf_rn(-2.f, u[1] + v[1], xnA + en1), c0 + 1);
                uint32_t k2 = distkey(__fmaf_rn(-2.f, u[2] + v[2], xnB + en0), c0);
                uint32_t k3 = distkey(__fmaf_rn(-2.f, u[3] + v[3], xnB + en1), c0 + 1);
                uint32_t hi;
                hi = max(m1A, k0); m1A = min(m1A, k0); m2A = min(m2A, hi);
                hi = max(m1A, k1); m1A = min(m1A, k1); m2A = min(m2A, hi);
                hi = max(m1B, k2); m1B = min(m1B, k2); m2B = min(m2B, hi);
                hi = max(m1B, k3); m1B = min(m1B, k3); m2B = min(m2B, hi);
            }
        }

        // merge across the 4 lanes of each row-group
        #pragma unroll
        for (int m = 1; m <= 2; m <<= 1) {
            uint32_t o1 = __shfl_xor_sync(0xffffffffu, m1A, m);
            uint32_t o2 = __shfl_xor_sync(0xffffffffu, m2A, m);
            uint32_t hi = max(m1A, o1);
            m1A = min(m1A, o1);
            m2A = min(min(m2A, o2), hi);
            o1 = __shfl_xor_sync(0xffffffffu, m1B, m);
            o2 = __shfl_xor_sync(0xffffffffu, m2B, m);
            hi = max(m1B, o1);
            m1B = min(m1B, o1);
            m2B = min(min(m2B, o2), hi);
        }

        // half1 publishes, half0 merges + writes idx + flags
        if (h == 1 && qid == 0) {
            sM1[mb + grp] = m1A; sM2[mb + grp] = m2A;
            sM1[mb + grp + 8] = m1B; sM2[mb + grp + 8] = m2B;
        }
        __syncthreads();
        if (h == 0 && qid == 0) {
            #pragma unroll
            for (int half = 0; half < 2; half++) {
                const int row = mb + grp + 8 * half;
                uint32_t m1 = half ? m1B : m1A;
                uint32_t m2 = half ? m2B : m2A;
                uint32_t o1 = sM1[row], o2 = sM2[row];
                uint32_t hi = max(m1, o1);
                m1 = min(m1, o1);
                m2 = min(min(m2, o2), hi);
                const int gtok = token0 + row;
                out[IDX_OFF + (size_t)gtok] = (float)(m1 & 0x1FFu);
                float margin = keyinv(m2) - keyinv(m1);
                if (!(margin > THETA)) {
                    unsigned p = atomicAdd(&g_flagn, 1u);
                    g_flags[p] = gtok;
                }
            }
        }
        __syncthreads();   // protect sA / sM before next tile
    }
}

// ======== K2: exact frozen recompute, one flagged token per thread, smem codebook ======
__global__ __launch_bounds__(512, 1) void vq_cleanup(
    const float* __restrict__ in, const float* __restrict__ emb,
    float* __restrict__ out)
{
    extern __shared__ float smem[];
    float* sE = smem;                 // NK x ESTR (raw f32)
    float* sEn = sE + NK * ESTR;      // NK (FROZEN norms)

    const int tid = threadIdx.x;
    const int wid = tid >> 5;
    const int lane = tid & 31;

    {
        const float4* e4 = (const float4*)emb;
        for (int i = tid; i < NK * ND / 4; i += 512) {
            int code = i >> 4, d4 = i & 15;
            float4 v = e4[i];
            *(float4*)(sE + code * ESTR + 4 * d4) = v;
        }
    }
    // FROZEN en: no-fma products, lane sums {l, l+32}, shfl tree 16..1
    for (int k = wid; k < NK; k += 16) {
        const float* e = emb + k * ND;
        float a = __fmul_rn(e[lane], e[lane]);
        float c = __fmul_rn(e[lane + 32], e[lane + 32]);
        float acc = __fadd_rn(a, c);
        #pragma unroll
        for (int off = 16; off; off >>= 1)
            acc = __fadd_rn(acc, __shfl_down_sync(0xffffffffu, acc, off));
        if (lane == 0) sEn[k] = acc;
    }
    __syncthreads();

    const unsigned count = g_flagn;

    for (unsigned fi = blockIdx.x * 512 + tid; fi < count; fi += gridDim.x * 512) {
        const int token = g_flags[fi];
        const int b = token >> 12, t = token & (NT - 1);

        const float* xp = in + (size_t)b * ND * NT + t;
        float x[ND];
        #pragma unroll
        for (int d = 0; d < ND; d++) x[d] = xp[(size_t)d * NT];

        // FROZEN xn: sequential ascending, no fma contraction
        float xn = 0.f;
        #pragma unroll
        for (int d = 0; d < ND; d++) xn = __fadd_rn(xn, __fmul_rn(x[d], x[d]));

        // FROZEN argmin: sequential ascending fma dot per code, 4 codes ILP,
        // combine fl(fl(xn+en) + fl(-2*dot)), strict < first-min.
        float best = 3.402823466e38f;
        int bidx = 0;
        for (int k0 = 0; k0 < NK; k0 += 4) {
            const float4* e0 = (const float4*)(sE + (k0 + 0) * ESTR);
            const float4* e1 = (const float4*)(sE + (k0 + 1) * ESTR);
            const float4* e2 = (const float4*)(sE + (k0 + 2) * ESTR);
            const float4* e3 = (const float4*)(sE + (k0 + 3) * ESTR);
            float a0 = 0.f, a1 = 0.f, a2 = 0.f, a3 = 0.f;
            #pragma unroll
            for (int j = 0; j < ND / 4; j++) {
                float4 v0 = e0[j], v1 = e1[j], v2 = e2[j], v3 = e3[j];
                a0 = __fmaf_rn(x[4*j+0], v0.x, a0);
                a1 = __fmaf_rn(x[4*j+0], v1.x, a1);
                a2 = __fmaf_rn(x[4*j+0], v2.x, a2);
                a3 = __fmaf_rn(x[4*j+0], v3.x, a3);
                a0 = __fmaf_rn(x[4*j+1], v0.y, a0);
                a1 = __fmaf_rn(x[4*j+1], v1.y, a1);
                a2 = __fmaf_rn(x[4*j+1], v2.y, a2);
                a3 = __fmaf_rn(x[4*j+1], v3.y, a3);
                a0 = __fmaf_rn(x[4*j+2], v0.z, a0);
                a1 = __fmaf_rn(x[4*j+2], v1.z, a1);
                a2 = __fmaf_rn(x[4*j+2], v2.z, a2);
                a3 = __fmaf_rn(x[4*j+2], v3.z, a3);
                a0 = __fmaf_rn(x[4*j+3], v0.w, a0);
                a1 = __fmaf_rn(x[4*j+3], v1.w, a1);
                a2 = __fmaf_rn(x[4*j+3], v2.w, a2);
                a3 = __fmaf_rn(x[4*j+3], v3.w, a3);
            }
            float d0 = __fadd_rn(__fadd_rn(xn, sEn[k0 + 0]), __fmul_rn(-2.f, a0));
            float d1 = __fadd_rn(__fadd_rn(xn, sEn[k0 + 1]), __fmul_rn(-2.f, a1));
            float d2 = __fadd_rn(__fadd_rn(xn, sEn[k0 + 2]), __fmul_rn(-2.f, a2));
            float d3 = __fadd_rn(__fadd_rn(xn, sEn[k0 + 3]), __fmul_rn(-2.f, a3));
            if (d0 < best) { best = d0; bidx = k0 + 0; }
            if (d1 < best) { best = d1; bidx = k0 + 1; }
            if (d2 < best) { best = d2; bidx = k0 + 2; }
            if (d3 < best) { best = d3; bidx = k0 + 3; }
        }
        out[IDX_OFF + (size_t)token] = (float)bidx;
    }
}

// ================= K3: gather + loss + histogram (from final indices) =================
__global__ __launch_bounds__(512, 1) void vq_gather(
    const float* __restrict__ in, const float* __restrict__ emb,
    float* __restrict__ out)
{
    __shared__ unsigned int sCount[NK];
    __shared__ float sLoss;
    const int tid = threadIdx.x;
    if (tid == 0) sLoss = 0.f;
    if (tid < NK) sCount[tid] = 0u;
    __syncthreads();

    const int token = blockIdx.x * 512 + tid;
    const int b = token >> 12, t = token & (NT - 1);
    const int k = (int)out[IDX_OFF + (size_t)token];

    atomicAdd(&sCount[k], 1u);

    const float* xp = in + (size_t)b * ND * NT + t;
    const float4* eb4 = (const float4*)(emb + k * ND);
    float* qp = out + Q_OFF + (size_t)b * ND * NT + t;
    float lsum = 0.f;
    #pragma unroll
    for (int j = 0; j < ND / 4; j++) {
        float4 v = eb4[j];
        float x0 = xp[(size_t)(4 * j + 0) * NT];
        float x1 = xp[(size_t)(4 * j + 1) * NT];
        float x2 = xp[(size_t)(4 * j + 2) * NT];
        float x3 = xp[(size_t)(4 * j + 3) * NT];
        qp[(size_t)(4 * j + 0) * NT] = v.x;
        qp[(size_t)(4 * j + 1) * NT] = v.y;
        qp[(size_t)(4 * j + 2) * NT] = v.z;
        qp[(size_t)(4 * j + 3) * NT] = v.w;
        float t0 = v.x - x0, t1 = v.y - x1, t2 = v.z - x2, t3 = v.w - x3;
        lsum = __fmaf_rn(t0, t0, lsum);
        lsum = __fmaf_rn(t1, t1, lsum);
        lsum = __fmaf_rn(t2, t2, lsum);
        lsum = __fmaf_rn(t3, t3, lsum);
    }
    #pragma unroll
    for (int off = 16; off; off >>= 1)
        lsum += __shfl_down_sync(0xffffffffu, lsum, off);
    if ((tid & 31) == 0) atomicAdd(&sLoss, lsum);
    __syncthreads();
    if (tid == 0) atomicAdd(&g_loss, sLoss);
    if (tid < NK) {
        unsigned c = sCount[tid];
        if (c) atomicAdd(&g_counts[tid], c);
    }
}

// ================= K4: finalize =================
__global__ void vq_final(float* __restrict__ out) {
    __shared__ float red[32];
    int tid = threadIdx.x;
    if (tid < 32) red[tid] = 0.f;
    __syncthreads();
    unsigned c = g_counts[tid];
    float p = (float)c / (float)NTOK;
    float term = p * logf(p + 1e-10f);
    #pragma unroll
    for (int off = 16; off; off >>= 1)
        term += __shfl_down_sync(0xffffffffu, term, off);
    if ((tid & 31) == 0) red[tid >> 5] = term;
    __syncthreads();
    if (tid < 32) {
        float v = red[tid];
        #pragma unroll
        for (int off = 16; off; off >>= 1)
            v += __shfl_down_sync(0xffffffffu, v, off);
        if (tid == 0) {
            out[PERP_OFF] = expf(-v);
            out[0] = 0.25f * g_loss / (float)((size_t)NTOK * ND);
        }
    }
}

extern "C" void kernel_launch(void* const* d_in, const int* in_sizes, int n_in,
                              void* d_out, int out_size) {
    const float* in  = (const float*)d_in[0];   // [32, 64, 4096]
    const float* emb = (const float*)d_in[1];   // [512, 64]
    float* out = (float*)d_out;

    size_t smem_g = (size_t)64 * 8 * 32 * sizeof(float2) +
                    (size_t)(TM * ESTR + NK + 512 + TM + 2 * TM) * sizeof(float);
    size_t smem_c = (size_t)(NK * ESTR + NK) * sizeof(float);
    cudaFuncSetAttribute(vq_gemm, cudaFuncAttributeMaxDynamicSharedMemorySize, (int)smem_g);
    cudaFuncSetAttribute(vq_cleanup, cudaFuncAttributeMaxDynamicSharedMemorySize, (int)smem_c);

    vq_init<<<1, 512>>>();
    vq_gemm<<<NCTA, 512, smem_g>>>(in, emb, out);
    vq_cleanup<<<NCTA, 512, smem_c>>>(in, emb, out);
    vq_gather<<<NTOK / 512, 512>>>(in, emb, out);
    vq_final<<<1, 512>>>(out);
}

// round 15
// speedup vs baseline: 4.9685x; 1.0565x over previous
#include <cuda_runtime.h>
#include <cuda_bf16.h>
#include <math.h>
#include <stdint.h>

// Problem constants
#define NB 32
#define ND 64
#define NT 4096
#define NK 512
#define NTOK (NB * NT)          // 131072 tokens
#define TM 128                  // tokens per tile
#define NTILES (NTOK / TM)      // 1024 tiles
#define ESTR 68                 // smem row stride (floats)

// Output layout (float32, reference tuple flattened in order)
#define Q_OFF     ((size_t)1)
#define PERP_OFF  ((size_t)1 + (size_t)NB * ND * NT)
#define IDX_OFF   (PERP_OFF + 1)

__device__ float g_loss;
__device__ unsigned int g_counts[NK];
__device__ unsigned int g_flagn;
__device__ unsigned int g_ticket;
__device__ int g_flags[NTOK];

// order-preserving uint encoding of float (handles negatives), idx in low 9 bits
__device__ __forceinline__ uint32_t distkey(float d, int col) {
    uint32_t u = __float_as_uint(d);
    u ^= (uint32_t)((int32_t)u >> 31) | 0x80000000u;
    return (u & 0xFFFFFE00u) | (uint32_t)col;
}
__device__ __forceinline__ float keyinv(uint32_t k) {
    uint32_t u = k & 0xFFFFFE00u;
    u = (u & 0x80000000u) ? (u ^ 0x80000000u) : ~u;
    return __uint_as_float(u);
}
__device__ __forceinline__ uint32_t bf2(float lo, float hi) {
    __nv_bfloat162 v = __floats2bfloat162_rn(lo, hi);
    return *(uint32_t*)&v;
}

// m16n8k16 bf16 mma: D += A(16x16,row) * B(16x8,col), f32 accumulate.
__device__ __forceinline__ void mma_bf16(float* d, const uint32_t* a, const uint32_t* b) {
    asm volatile(
        "mma.sync.aligned.m16n8k16.row.col.f32.bf16.bf16.f32 "
        "{%0,%1,%2,%3}, {%4,%5,%6,%7}, {%8,%9}, {%0,%1,%2,%3};"
        : "+f"(d[0]), "+f"(d[1]), "+f"(d[2]), "+f"(d[3])
        : "r"(a[0]), "r"(a[1]), "r"(a[2]), "r"(a[3]), "r"(b[0]), "r"(b[1]));
}

// ========== K1: bf16 mma GEMM (2 CTA/SM), argmin + provable margin flag ==========
__global__ __launch_bounds__(512, 2) void vq_gemm(
    const float* __restrict__ in, const float* __restrict__ emb,
    float* __restrict__ out)
{
    extern __shared__ float smem[];
    // Fragment-packed bf16 B: [ntile(64)][kk(4)][lane(32)] uint2
    //   lane l = (g = l>>2, t = l&3); code = 8*nt + g; d0 = 16*kk + 2*t
    //   .x = bf16x2(E[code][d0],   E[code][d0+1])   (k-low half)
    //   .y = bf16x2(E[code][d0+8], E[code][d0+9])   (k-high half)
    uint2* sBf  = (uint2*)smem;                 // 8192 uint2 = 64 KB
    float* sA   = (float*)(sBf + 64 * 4 * 32);  // TM x ESTR
    float* sEn  = sA + TM * ESTR;               // NK
    float* sXnP = sEn + NK;                     // 512 partials
    float* sXn  = sXnP + 512;                   // TM
    uint32_t* sM1 = (uint32_t*)(sXn + TM);      // TM (half1 best key)
    uint32_t* sM2 = sM1 + TM;                   // TM (half1 second key)
    float* sEmx = (float*)(sM2 + TM);           // [16] per-warp max-en partials
    __shared__ int sTile;

    const int tid = threadIdx.x;
    const int wid = tid >> 5;
    const int lane = tid & 31;
    const int grp = lane >> 2;                  // 0..7
    const int qid = lane & 3;                   // 0..3
    const int h   = wid >> 3;                   // n-half (ntiles [h*32, h*32+32))
    const int mb  = (wid & 7) * 16;             // m-block base row

    // ---- ONE-TIME staging: fragment-packed bf16 B ----
    for (int i = tid; i < 64 * 4 * 32; i += 512) {
        int nt = i >> 7, kk = (i >> 5) & 3, ln = i & 31;
        const float* e = emb + (8 * nt + (ln >> 2)) * ND + 16 * kk + 2 * (ln & 3);
        sBf[i] = make_uint2(bf2(e[0], e[1]), bf2(e[8], e[9]));
    }
    // ---- en (coalesced warp-tree, sloppy ok) + per-warp max ----
    {
        float wmax = 0.f;
        for (int k = wid; k < NK; k += 16) {
            const float* e = emb + k * ND;
            float acc = __fmaf_rn(e[lane], e[lane], __fmul_rn(e[lane + 32], e[lane + 32]));
            #pragma unroll
            for (int off = 16; off; off >>= 1)
                acc += __shfl_down_sync(0xffffffffu, acc, off);
            acc = __shfl_sync(0xffffffffu, acc, 0);
            if (lane == 0) sEn[k] = acc;
            wmax = fmaxf(wmax, acc);
        }
        if (lane == 0) sEmx[wid] = wmax;
    }
    __syncthreads();
    float emax2 = 0.f;                          // max ||e||^2
    #pragma unroll
    for (int i = 0; i < 16; i++) emax2 = fmaxf(emax2, sEmx[i]);
    const float emax = sqrtf(emax2);

    // ---- ticketed tile loop ----
    for (;;) {
        if (tid == 0) sTile = (int)atomicAdd(&g_ticket, 1u);
        __syncthreads();
        const int tile = sTile;
        if (tile >= NTILES) break;

        const int token0 = tile * TM;
        const int b = token0 >> 12;
        const int t0 = token0 & (NT - 1);

        // A staging: token = tid&127, quarter of d each (coalesced)
        {
            const int tok = tid & 127, part = tid >> 7;
            const float* xp = in + (size_t)b * ND * NT + (t0 + tok);
            float p = 0.f;
            float* ar = sA + tok * ESTR + part * 16;
            #pragma unroll
            for (int i = 0; i < 16; i++) {
                float x = xp[(size_t)(part * 16 + i) * NT];
                ar[i] = x;
                p = __fmaf_rn(x, x, p);
            }
            sXnP[tok * 4 + part] = p;
        }
        __syncthreads();
        if (tid < TM) {
            const float* p = sXnP + tid * 4;
            sXn[tid] = (p[0] + p[1]) + (p[2] + p[3]);
        }
        __syncthreads();

        // A fragments (bf16): rows (mb+grp, mb+grp+8), k-chunk kk of 16
        uint32_t ah[4][4];
        #pragma unroll
        for (int kk = 0; kk < 4; kk++) {
            const float* r0 = sA + (mb + grp) * ESTR + 16 * kk + 2 * qid;
            const float* r8 = sA + (mb + grp + 8) * ESTR + 16 * kk + 2 * qid;
            ah[kk][0] = bf2(r0[0], r0[1]);
            ah[kk][1] = bf2(r8[0], r8[1]);
            ah[kk][2] = bf2(r0[8], r0[9]);
            ah[kk][3] = bf2(r8[8], r8[9]);
        }
        const float xnA = sXn[mb + grp];
        const float xnB = sXn[mb + grp + 8];

        uint32_t m1A = 0xFFFFFFFFu, m2A = 0xFFFFFFFFu;
        uint32_t m1B = 0xFFFFFFFFu, m2B = 0xFFFFFFFFu;

        // n-loop: 2 n-tiles per iteration (independent chains), 4 mma each
        #pragma unroll 1
        for (int nt = 0; nt < 32; nt += 2) {
            const int ntile = h * 32 + nt;
            const uint2* f0 = sBf + ntile * 128 + lane;
            const uint2* f1 = f0 + 128;
            float p0[4] = {0.f, 0.f, 0.f, 0.f};
            float q0[4] = {0.f, 0.f, 0.f, 0.f};
            #pragma unroll
            for (int kk = 0; kk < 4; kk++) {
                uint2 b0 = f0[kk * 32];
                uint2 b1 = f1[kk * 32];
                mma_bf16(p0, ah[kk], (const uint32_t*)&b0);
                mma_bf16(q0, ah[kk], (const uint32_t*)&b1);
            }
            #pragma unroll
            for (int half = 0; half < 2; half++) {
                const float* u = half ? q0 : p0;
                const int c0 = (ntile + half) * 8 + 2 * qid;
                const float en0 = sEn[c0], en1 = sEn[c0 + 1];
                uint32_t k0 = distkey(__fmaf_rn(-2.f, u[0], xnA + en0), c0);
                uint32_t k1 = distkey(__fmaf_rn(-2.f, u[1], xnA + en1), c0 + 1);
                uint32_t k2 = distkey(__fmaf_rn(-2.f, u[2], xnB + en0), c0);
                uint32_t k3 = distkey(__fmaf_rn(-2.f, u[3], xnB + en1), c0 + 1);
                uint32_t hi;
                hi = max(m1A, k0); m1A = min(m1A, k0); m2A = min(m2A, hi);
                hi = max(m1A, k1); m1A = min(m1A, k1); m2A = min(m2A, hi);
                hi = max(m1B, k2); m1B = min(m1B, k2); m2B = min(m2B, hi);
                hi = max(m1B, k3); m1B = min(m1B, k3); m2B = min(m2B, hi);
            }
        }

        // merge across the 4 lanes of each row-group
        #pragma unroll
        for (int m = 1; m <= 2; m <<= 1) {
            uint32_t o1 = __shfl_xor_sync(0xffffffffu, m1A, m);
            uint32_t o2 = __shfl_xor_sync(0xffffffffu, m2A, m);
            uint32_t hi = max(m1A, o1);
            m1A = min(m1A, o1);
            m2A = min(min(m2A, o2), hi);
            o1 = __shfl_xor_sync(0xffffffffu, m1B, m);
            o2 = __shfl_xor_sync(0xffffffffu, m2B, m);
            hi = max(m1B, o1);
            m1B = min(m1B, o1);
            m2B = min(min(m2B, o2), hi);
        }

        // half1 publishes, half0 merges + writes idx + flags
        if (h == 1 && qid == 0) {
            sM1[mb + grp] = m1A; sM2[mb + grp] = m2A;
            sM1[mb + grp + 8] = m1B; sM2[mb + grp + 8] = m2B;
        }
        __syncthreads();
        if (h == 0 && qid == 0) {
            #pragma unroll
            for (int half = 0; half < 2; half++) {
                const int row = mb + grp + 8 * half;
                uint32_t m1 = half ? m1B : m1A;
                uint32_t m2 = half ? m2B : m2A;
                uint32_t o1 = sM1[row], o2 = sM2[row];
                uint32_t hi = max(m1, o1);
                m1 = min(m1, o1);
                m2 = min(min(m2, o2), hi);
                const int gtok = token0 + row;
                out[IDX_OFF + (size_t)gtok] = (float)(m1 & 0x1FFu);
                // PROVABLE bound: margin err <= 2^-6 * |x| * Emax (bf16-rn inputs)
                //   + key-mask/combine slop 0.02. Above it, frozen winner == bf16 winner.
                float margin = keyinv(m2) - keyinv(m1);
                float xnrm = sqrtf(half ? xnB : xnA);
                // NOTE: xnA/xnB belong to (mb+grp) rows of half0 warps; recompute safely:
                float bound = 0.015625f * sqrtf(sXn[row]) * emax + 0.02f;
                (void)xnrm;
                if (!(margin > bound)) {       // tiny margin (or NaN) -> exact path
                    unsigned p = atomicAdd(&g_flagn, 1u);
                    g_flags[p] = gtok;
                }
            }
        }
        __syncthreads();   // protect sA / sM / sTile before next tile
    }
}

// ======== K2: exact frozen recompute, one flagged token per thread, smem codebook ======
__global__ __launch_bounds__(512, 1) void vq_cleanup(
    const float* __restrict__ in, const float* __restrict__ emb,
    float* __restrict__ out)
{
    extern __shared__ float smem[];
    float* sE = smem;                 // NK x ESTR (raw f32)
    float* sEn = sE + NK * ESTR;      // NK (FROZEN norms)

    const int tid = threadIdx.x;
    const int wid = tid >> 5;
    const int lane = tid & 31;

    {
        const float4* e4 = (const float4*)emb;
        for (int i = tid; i < NK * ND / 4; i += 512) {
            int code = i >> 4, d4 = i & 15;
            float4 v = e4[i];
            *(float4*)(sE + code * ESTR + 4 * d4) = v;
        }
    }
    // FROZEN en: no-fma products, lane sums {l, l+32}, shfl tree 16..1
    for (int k = wid; k < NK; k += 16) {
        const float* e = emb + k * ND;
        float a = __fmul_rn(e[lane], e[lane]);
        float c = __fmul_rn(e[lane + 32], e[lane + 32]);
        float acc = __fadd_rn(a, c);
        #pragma unroll
        for (int off = 16; off; off >>= 1)
            acc = __fadd_rn(acc, __shfl_down_sync(0xffffffffu, acc, off));
        if (lane == 0) sEn[k] = acc;
    }
    __syncthreads();

    const unsigned count = g_flagn;

    for (unsigned fi = blockIdx.x * 512 + tid; fi < count; fi += gridDim.x * 512) {
        const int token = g_flags[fi];
        const int b = token >> 12, t = token & (NT - 1);

        const float* xp = in + (size_t)b * ND * NT + t;
        float x[ND];
        #pragma unroll
        for (int d = 0; d < ND; d++) x[d] = xp[(size_t)d * NT];

        // FROZEN xn: sequential ascending, no fma contraction
        float xn = 0.f;
        #pragma unroll
        for (int d = 0; d < ND; d++) xn = __fadd_rn(xn, __fmul_rn(x[d], x[d]));

        // FROZEN argmin: sequential ascending fma dot per code, 4 codes ILP,
        // combine fl(fl(xn+en) + fl(-2*dot)), strict < first-min.
        float best = 3.402823466e38f;
        int bidx = 0;
        for (int k0 = 0; k0 < NK; k0 += 4) {
            const float4* e0 = (const float4*)(sE + (k0 + 0) * ESTR);
            const float4* e1 = (const float4*)(sE + (k0 + 1) * ESTR);
            const float4* e2 = (const float4*)(sE + (k0 + 2) * ESTR);
            const float4* e3 = (const float4*)(sE + (k0 + 3) * ESTR);
            float a0 = 0.f, a1 = 0.f, a2 = 0.f, a3 = 0.f;
            #pragma unroll
            for (int j = 0; j < ND / 4; j++) {
                float4 v0 = e0[j], v1 = e1[j], v2 = e2[j], v3 = e3[j];
                a0 = __fmaf_rn(x[4*j+0], v0.x, a0);
                a1 = __fmaf_rn(x[4*j+0], v1.x, a1);
                a2 = __fmaf_rn(x[4*j+0], v2.x, a2);
                a3 = __fmaf_rn(x[4*j+0], v3.x, a3);
                a0 = __fmaf_rn(x[4*j+1], v0.y, a0);
                a1 = __fmaf_rn(x[4*j+1], v1.y, a1);
                a2 = __fmaf_rn(x[4*j+1], v2.y, a2);
                a3 = __fmaf_rn(x[4*j+1], v3.y, a3);
                a0 = __fmaf_rn(x[4*j+2], v0.z, a0);
                a1 = __fmaf_rn(x[4*j+2], v1.z, a1);
                a2 = __fmaf_rn(x[4*j+2], v2.z, a2);
                a3 = __fmaf_rn(x[4*j+2], v3.z, a3);
                a0 = __fmaf_rn(x[4*j+3], v0.w, a0);
                a1 = __fmaf_rn(x[4*j+3], v1.w, a1);
                a2 = __fmaf_rn(x[4*j+3], v2.w, a2);
                a3 = __fmaf_rn(x[4*j+3], v3.w, a3);
            }
            float d0 = __fadd_rn(__fadd_rn(xn, sEn[k0 + 0]), __fmul_rn(-2.f, a0));
            float d1 = __fadd_rn(__fadd_rn(xn, sEn[k0 + 1]), __fmul_rn(-2.f, a1));
            float d2 = __fadd_rn(__fadd_rn(xn, sEn[k0 + 2]), __fmul_rn(-2.f, a2));
            float d3 = __fadd_rn(__fadd_rn(xn, sEn[k0 + 3]), __fmul_rn(-2.f, a3));
            if (d0 < best) { best = d0; bidx = k0 + 0; }
            if (d1 < best) { best = d1; bidx = k0 + 1; }
            if (d2 < best) { best = d2; bidx = k0 + 2; }
            if (d3 < best) { best = d3; bidx = k0 + 3; }
        }
        out[IDX_OFF + (size_t)token] = (float)bidx;
    }
}

// ================= K3: gather + loss + histogram (from final indices) =================
__global__ __launch_bounds__(512, 1) void vq_gather(
    const float* __restrict__ in, const float* __restrict__ emb,
    float* __restrict__ out)
{
    __shared__ unsigned int sCount[NK];
    __shared__ float sLoss;
    const int tid = threadIdx.x;
    if (tid == 0) sLoss = 0.f;
    if (tid < NK) sCount[tid] = 0u;
    __syncthreads();

    const int token = blockIdx.x * 512 + tid;
    const int b = token >> 12, t = token & (NT - 1);
    const int k = (int)out[IDX_OFF + (size_t)token];

    atomicAdd(&sCount[k], 1u);

    const float* xp = in + (size_t)b * ND * NT + t;
    const float4* eb4 = (const float4*)(emb + k * ND);
    float* qp = out + Q_OFF + (size_t)b * ND * NT + t;
    float lsum = 0.f;
    #pragma unroll
    for (int j = 0; j < ND / 4; j++) {
        float4 v = eb4[j];
        float x0 = xp[(size_t)(4 * j + 0) * NT];
        float x1 = xp[(size_t)(4 * j + 1) * NT];
        float x2 = xp[(size_t)(4 * j + 2) * NT];
        float x3 = xp[(size_t)(4 * j + 3) * NT];
        qp[(size_t)(4 * j + 0) * NT] = v.x;
        qp[(size_t)(4 * j + 1) * NT] = v.y;
        qp[(size_t)(4 * j + 2) * NT] = v.z;
        qp[(size_t)(4 * j + 3) * NT] = v.w;
        float t0 = v.x - x0, t1 = v.y - x1, t2 = v.z - x2, t3 = v.w - x3;
        lsum = __fmaf_rn(t0, t0, lsum);
        lsum = __fmaf_rn(t1, t1, lsum);
        lsum = __fmaf_rn(t2, t2, lsum);
        lsum = __fmaf_rn(t3, t3, lsum);
    }
    #pragma unroll
    for (int off = 16; off; off >>= 1)
        lsum += __shfl_down_sync(0xffffffffu, lsum, off);
    if ((tid & 31) == 0) atomicAdd(&sLoss, lsum);
    __syncthreads();
    if (tid == 0) atomicAdd(&g_loss, sLoss);
    if (tid < NK) {
        unsigned c = sCount[tid];
        if (c) atomicAdd(&g_counts[tid], c);
    }
}

// ======= K4: finalize + self-prime globals for the next call (replaces vq_init) =======
__global__ void vq_final(float* __restrict__ out) {
    __shared__ float red[32];
    int tid = threadIdx.x;
    if (tid < 32) red[tid] = 0.f;
    __syncthreads();
    unsigned c = g_counts[tid];
    float p = (float)c / (float)NTOK;
    float term = p * logf(p + 1e-10f);
    #pragma unroll
    for (int off = 16; off; off >>= 1)
        term += __shfl_down_sync(0xffffffffu, term, off);
    if ((tid & 31) == 0) red[tid >> 5] = term;
    __syncthreads();
    if (tid < 32) {
        float v = red[tid];
        #pragma unroll
        for (int off = 16; off; off >>= 1)
            v += __shfl_down_sync(0xffffffffu, v, off);
        if (tid == 0) {
            out[PERP_OFF] = expf(-v);
            out[0] = 0.25f * g_loss / (float)((size_t)NTOK * ND);
            g_loss = 0.f;
            g_flagn = 0u;
            g_ticket = 0u;
        }
    }
    g_counts[tid] = 0u;     // reset for next call (globals start zero-initialized)
}

extern "C" void kernel_launch(void* const* d_in, const int* in_sizes, int n_in,
                              void* d_out, int out_size) {
    const float* in  = (const float*)d_in[0];   // [32, 64, 4096]
    const float* emb = (const float*)d_in[1];   // [512, 64]
    float* out = (float*)d_out;

    size_t smem_g = (size_t)64 * 4 * 32 * sizeof(uint2) +
                    (size_t)(TM * ESTR + NK + 512 + TM) * sizeof(float) +
                    (size_t)(2 * TM) * sizeof(uint32_t) + 16 * sizeof(float) + 64;
    size_t smem_c = (size_t)(NK * ESTR + NK) * sizeof(float);
    cudaFuncSetAttribute(vq_gemm, cudaFuncAttributeMaxDynamicSharedMemorySize, (int)smem_g);
    cudaFuncSetAttribute(vq_cleanup, cudaFuncAttributeMaxDynamicSharedMemorySize, (int)smem_c);

    vq_gemm<<<296, 512, smem_g>>>(in, emb, out);
    vq_cleanup<<<148, 512, smem_c>>>(in, emb, out);
    vq_gather<<<NTOK / 512, 512>>>(in, emb, out);
    vq_final<<<1, 512>>>(out);
}